// round 9
// baseline (speedup 1.0000x reference)
#include <cuda_runtime.h>
#include <cuda_bf16.h>
#include <math.h>

#define NN    512
#define EPN   511
#define FD    128
#define TILE  128
#define NTILE 4
#define NTHR  512

__device__ float g_vec0[NN * 3];
__device__ float g_vec [NN * 3];
__device__ float g_hf  [NN * FD];
__device__ float g_hs  [NN * FD];
__device__ float g_hr  [NN * FD];
__device__ float g_magg[NN * FD];
__device__ float g_vac [NN * 3];
// 8 matrices (2 blocks x {We1,We2,Wx0,Wx1}) as T[n][k] images, 64KB each: [hi|lo]
__device__ __align__(16) __nv_bfloat16 g_wb[8 * 32768];

__device__ __forceinline__ float siluf(float x) { return x / (1.f + __expf(-x)); }
__device__ __forceinline__ float sigmf(float x) { return 1.f / (1.f + __expf(-x)); }

__device__ __forceinline__ unsigned smem_u32(const void* p) {
    unsigned a;
    asm("{ .reg .u64 t; cvta.to.shared.u64 t, %1; cvt.u32.u64 %0, t; }" : "=r"(a) : "l"(p));
    return a;
}
__device__ __forceinline__ void cpasync16(unsigned d, const void* g) {
    asm volatile("cp.async.cg.shared.global [%0], [%1], 16;" :: "r"(d), "l"(g));
}
#define CP_COMMIT() asm volatile("cp.async.commit_group;" ::: "memory")
#define CP_WAIT0()  asm volatile("cp.async.wait_group 0;"  ::: "memory")

__device__ __forceinline__ void ldsm4(unsigned* r, unsigned a) {
    asm volatile("ldmatrix.sync.aligned.m8n8.x4.shared.b16 {%0,%1,%2,%3}, [%4];"
        : "=r"(r[0]), "=r"(r[1]), "=r"(r[2]), "=r"(r[3]) : "r"(a));
}
__device__ __forceinline__ void mma16816(float* c, const unsigned* a,
                                         unsigned b0, unsigned b1) {
    asm volatile("mma.sync.aligned.m16n8k16.row.col.f32.bf16.bf16.f32 "
        "{%0,%1,%2,%3}, {%4,%5,%6,%7}, {%8,%9}, {%0,%1,%2,%3};"
        : "+f"(c[0]), "+f"(c[1]), "+f"(c[2]), "+f"(c[3])
        : "r"(a[0]), "r"(a[1]), "r"(a[2]), "r"(a[3]), "r"(b0), "r"(b1));
}

// image layout: row-major [row][k], 256B rows, 16B chunks XOR-swizzled by row&7
__device__ __forceinline__ int img_off(int e, int c) {
    return (e << 8) + ((((c >> 3) ^ (e & 7))) << 4) + ((c & 7) << 1);
}
__device__ __forceinline__ void st_split2(char* hb, char* lb, int off,
                                          float v0, float v1) {
    __nv_bfloat16 h0 = __float2bfloat16(v0), h1 = __float2bfloat16(v1);
    __nv_bfloat16 l0 = __float2bfloat16(v0 - __bfloat162float(h0));
    __nv_bfloat16 l1 = __float2bfloat16(v1 - __bfloat162float(h1));
    *reinterpret_cast<unsigned*>(hb + off) =
        (unsigned)__bfloat16_as_ushort(h0) | ((unsigned)__bfloat16_as_ushort(h1) << 16);
    *reinterpret_cast<unsigned*>(lb + off) =
        (unsigned)__bfloat16_as_ushort(l0) | ((unsigned)__bfloat16_as_ushort(l1) << 16);
}

struct __align__(16) ES {
    char xhi[32768]; char xlo[32768];   // act0 / m images [e][k]
    char yhi[32768]; char ylo[32768];   // GEMM1/3 output images
    char bbuf[65536];                   // current weight pair {hi|lo}, T[n][k]
    float dv[3 * TILE], len[TILE], l2[TILE], gate[TILE], pxs[TILE];
    float gpart[4 * TILE];
    float w0[FD], hrb[FD], winf[FD], wxo[FD];
    float bb1[FD], bb2[FD], bbx0[FD], bbx1[FD];
    float maggs[4 * FD], vred[3 * TILE], vaccs[4], rvec[3];
    int   sidx[TILE];
};

__device__ __forceinline__ void loadB(char* dst, const __nv_bfloat16* blob, int t) {
    unsigned sd = smem_u32(dst);
    const float4* src = reinterpret_cast<const float4*>(blob);
#pragma unroll
    for (int q = 0; q < 8; q++) { int u = t + q * NTHR; cpasync16(sd + u * 16, src + u); }
    CP_COMMIT();
}

// C[128e][128c] = split3( A @ W ); 16 warps, each a 32e x 32c tile.
// epilogue: +bias (opt silu / dot / store split). Internally:
// mma loops -> syncthreads -> cp.async next weight blob -> epilogue.
template <bool ACT, bool DOT, bool STORE>
__device__ __forceinline__ void gemm_tc(ES* S, const char* Ahi, const char* Alo,
                                        const __nv_bfloat16* nextblob,
                                        const float* bias, const float* dw,
                                        char* Ohi, char* Olo, int t)
{
    const int w = t >> 5, lane = t & 31;
    const int e0 = (w >> 2) * 32, c0 = (w & 3) * 32;
    const unsigned l7 = lane & 7;
    float acc[2][4][4];
#pragma unroll
    for (int mt = 0; mt < 2; mt++)
#pragma unroll
        for (int nt = 0; nt < 4; nt++)
#pragma unroll
            for (int q = 0; q < 4; q++) acc[mt][nt][q] = 0.f;

    const unsigned arow = e0 + (lane & 15);
    const unsigned acb  = lane >> 4;
    const unsigned brow = c0 + ((lane >> 4) << 3) + l7;
    const unsigned bcb  = (lane >> 3) & 1;

#pragma unroll
    for (int term = 0; term < 3; term++) {
        const char* As = (term == 2) ? Alo : Ahi;
        const char* Bs = S->bbuf + ((term == 1) ? 32768 : 0);
        unsigned ab = smem_u32(As) + arow * 256;
        unsigned bb = smem_u32(Bs) + brow * 256;
#pragma unroll
        for (int ks = 0; ks < 8; ks++) {
            unsigned a0[4], a1[4];
            unsigned ach = (((unsigned)(ks << 1)) | acb) ^ l7;
            ldsm4(a0, ab + (ach << 4));
            ldsm4(a1, ab + 16 * 256 + (ach << 4));
            unsigned bch = (((unsigned)(ks << 1)) | bcb) ^ l7;
#pragma unroll
            for (int p = 0; p < 2; p++) {
                unsigned b[4];
                ldsm4(b, bb + p * 16 * 256 + (bch << 4));
                mma16816(acc[0][2 * p],     a0, b[0], b[1]);
                mma16816(acc[0][2 * p + 1], a0, b[2], b[3]);
                mma16816(acc[1][2 * p],     a1, b[0], b[1]);
                mma16816(acc[1][2 * p + 1], a1, b[2], b[3]);
            }
        }
    }
    __syncthreads();                 // all warps done reading bbuf + A images
    loadB(S->bbuf, nextblob, t);     // stream next weights under the epilogue

    const int r = lane >> 2, n2 = (lane & 3) * 2;
    float drow[2][2] = {{0.f, 0.f}, {0.f, 0.f}};
#pragma unroll
    for (int mt = 0; mt < 2; mt++) {
        int eA = e0 + mt * 16 + r;
#pragma unroll
        for (int nt = 0; nt < 4; nt++) {
            int c = c0 + nt * 8 + n2;
            float b0v = bias[c], b1v = bias[c + 1];
            float v00 = acc[mt][nt][0] + b0v, v01 = acc[mt][nt][1] + b1v;
            float v10 = acc[mt][nt][2] + b0v, v11 = acc[mt][nt][3] + b1v;
            if (ACT) { v00 = siluf(v00); v01 = siluf(v01);
                       v10 = siluf(v10); v11 = siluf(v11); }
            if (DOT) {
                drow[mt][0] += v00 * dw[c] + v01 * dw[c + 1];
                drow[mt][1] += v10 * dw[c] + v11 * dw[c + 1];
            }
            if (STORE) {
                st_split2(Ohi, Olo, img_off(eA, c), v00, v01);
                st_split2(Ohi, Olo, img_off(eA + 8, c), v10, v11);
            }
        }
    }
    if (DOT) {
#pragma unroll
        for (int mt = 0; mt < 2; mt++)
#pragma unroll
            for (int hb = 0; hb < 2; hb++) {
                float v = drow[mt][hb];
                v += __shfl_xor_sync(0xffffffffu, v, 1);
                v += __shfl_xor_sync(0xffffffffu, v, 2);
                if ((lane & 3) == 0)
                    S->gpart[(w & 3) * TILE + e0 + mt * 16 + hb * 8 + r] = v;
            }
    }
}

__global__ void __launch_bounds__(NTHR, 1)
kedge(const int* __restrict__ senders, const float* __restrict__ We0r0,
      const float* __restrict__ be1, const float* __restrict__ be2,
      const float* __restrict__ Winf, const float* __restrict__ binfp,
      const float* __restrict__ bx0, const float* __restrict__ bx1,
      const float* __restrict__ Wxo, const float* __restrict__ bxop, int blk)
{
    extern __shared__ char smraw[];
    ES* S = reinterpret_cast<ES*>(smraw);
    const int t = threadIdx.x, i = blockIdx.x;
    const __nv_bfloat16* wb = g_wb + blk * 4 * 32768;

    if (t < FD) {
        S->w0[t] = We0r0[t]; S->hrb[t] = g_hr[i * FD + t];
        S->winf[t] = Winf[t]; S->wxo[t] = Wxo[t];
        S->bb1[t] = be1[t]; S->bb2[t] = be2[t];
        S->bbx0[t] = bx0[t]; S->bbx1[t] = bx1[t];
    }
    if (t < 4) S->vaccs[t] = 0.f;
    if (t < 3) S->rvec[t] = g_vec[i * 3 + t];
    const float binf_s = binfp[0], bxo_s = bxop[0];

    loadB(S->bbuf, wb, t);          // We1
    __syncthreads();

    const int kk = t & 127, hh = t >> 7;   // hh in 0..3: edge quarter
    float mreg = 0.f;

    for (int tile = 0; tile < NTILE; tile++) {
        if (t < TILE) {                                  // stage 1
            int je = tile * TILE + t;
            bool valid = je < EPN;
            int s = valid ? senders[i * EPN + je] : i;
            S->sidx[t] = s;
            float d0 = 0.f, d1 = 0.f, d2 = 0.f;
            if (valid) {
                d0 = S->rvec[0] - g_vec[s * 3 + 0];
                d1 = S->rvec[1] - g_vec[s * 3 + 1];
                d2 = S->rvec[2] - g_vec[s * 3 + 2];
            }
            S->dv[t * 3] = d0; S->dv[t * 3 + 1] = d1; S->dv[t * 3 + 2] = d2;
            float dot = d0 * d0 + d1 * d1 + d2 * d2 + 1e-20f;
            S->l2[t] = valid ? dot : 0.f;
            S->len[t] = sqrtf(dot);
        }
        __syncthreads();
        {                                                // stage 2: act0 -> X
            int e = t >> 2, kh = t & 3;
            int s = S->sidx[e];
            float l2v = S->l2[e];
            const float* hsr = g_hs + s * FD + kh * 32;
#pragma unroll 8
            for (int j = 0; j < 32; j += 2) {
                int c = kh * 32 + j;
                float v0 = siluf(l2v * S->w0[c]     + hsr[j]     + S->hrb[c]);
                float v1 = siluf(l2v * S->w0[c + 1] + hsr[j + 1] + S->hrb[c + 1]);
                st_split2(S->xhi, S->xlo, img_off(e, c), v0, v1);
            }
        }
        CP_WAIT0();
        __syncthreads();

        // G1: Y = silu(X @ We1 + be1)
        gemm_tc<true, false, true>(S, S->xhi, S->xlo, wb + 1 * 32768,
                                   S->bb1, 0, S->yhi, S->ylo, t);
        CP_WAIT0(); __syncthreads();

        // G2: m = Y @ We2 + be2 -> X; dot winf
        gemm_tc<false, true, true>(S, S->yhi, S->ylo, wb + 2 * 32768,
                                   S->bb2, S->winf, S->xhi, S->xlo, t);
        CP_WAIT0(); __syncthreads();
        if (t < TILE) {
            bool valid = (tile * TILE + t) < EPN;
            S->gate[t] = valid ? sigmf(binf_s + S->gpart[t] + S->gpart[TILE + t]
                                       + S->gpart[2 * TILE + t] + S->gpart[3 * TILE + t])
                               : 0.f;
        }
        __syncthreads();
        {                                                // magg partial from X (m)
            float acc = 0.f;
#pragma unroll 4
            for (int e = hh * 32; e < hh * 32 + 32; e++) {
                int adr = img_off(e, kk);
                float m = __bfloat162float(*reinterpret_cast<__nv_bfloat16*>(S->xhi + adr))
                        + __bfloat162float(*reinterpret_cast<__nv_bfloat16*>(S->xlo + adr));
                acc += m * S->gate[e];
            }
            mreg += acc;
        }

        // G3: Y = silu(X @ Wx0 + bx0)
        gemm_tc<true, false, true>(S, S->xhi, S->xlo, wb + 3 * 32768,
                                   S->bbx0, 0, S->yhi, S->ylo, t);
        CP_WAIT0(); __syncthreads();

        // G4: px partial = silu(Y @ Wx1 + bx1) . wxo  (no store)
        gemm_tc<true, true, false>(S, S->yhi, S->ylo, wb,
                                   S->bbx1, S->wxo, S->yhi, S->ylo, t);
        __syncthreads();
        if (t < TILE)
            S->pxs[t] = (bxo_s + S->gpart[t] + S->gpart[TILE + t]
                         + S->gpart[2 * TILE + t] + S->gpart[3 * TILE + t])
                        / (1.f + S->len[t]);
        __syncthreads();
        if (t < TILE) {                                  // vac partial
            float p = S->pxs[t];
            S->vred[t] = p * S->dv[t * 3];
            S->vred[TILE + t] = p * S->dv[t * 3 + 1];
            S->vred[2 * TILE + t] = p * S->dv[t * 3 + 2];
        }
        __syncthreads();
        if (t < 96) {
            int c = t >> 5, l = t & 31;
            const float* vr = S->vred + c * TILE;
            float v = (vr[l] + vr[l + 32]) + (vr[l + 64] + vr[l + 96]);
#pragma unroll
            for (int o = 16; o; o >>= 1) v += __shfl_down_sync(0xffffffffu, v, o);
            if (l == 0) S->vaccs[c] += v;
        }
        __syncthreads();
    }

    S->maggs[hh * FD + kk] = mreg;
    __syncthreads();
    if (t < FD)
        g_magg[i * FD + t] = (S->maggs[t] + S->maggs[FD + t]
                              + S->maggs[2 * FD + t] + S->maggs[3 * FD + t])
                             * rsqrtf(511.f);
    if (t < 3) g_vac[i * 3 + t] = S->vaccs[t] * (1.f / 511.f);
}

// weights -> T[n][k] bf16 hi/lo swizzled images (one CTA per matrix)
__global__ void __launch_bounds__(256) kwprep(
    const float* __restrict__ We1, const float* __restrict__ We2,
    const float* __restrict__ Wx0, const float* __restrict__ Wx1)
{
    int m = blockIdx.x, b = m >> 2, g = m & 3;
    const float* W = (g == 0 ? We1 : g == 1 ? We2 : g == 2 ? Wx0 : Wx1) + b * FD * FD;
    char* blob = reinterpret_cast<char*>(g_wb + m * 32768);
    int t = threadIdx.x, n = t & 127, kh = t >> 7;
    for (int kc = 0; kc < 8; kc++) {
        int kchunk = kh * 8 + kc;
        unsigned qh[4], ql[4];
#pragma unroll
        for (int u = 0; u < 4; u++) {
            int k = kchunk * 8 + u * 2;
            float x0 = W[k * FD + n], x1 = W[(k + 1) * FD + n];
            __nv_bfloat16 h0 = __float2bfloat16(x0), h1 = __float2bfloat16(x1);
            __nv_bfloat16 l0 = __float2bfloat16(x0 - __bfloat162float(h0));
            __nv_bfloat16 l1 = __float2bfloat16(x1 - __bfloat162float(h1));
            qh[u] = (unsigned)__bfloat16_as_ushort(h0) | ((unsigned)__bfloat16_as_ushort(h1) << 16);
            ql[u] = (unsigned)__bfloat16_as_ushort(l0) | ((unsigned)__bfloat16_as_ushort(l1) << 16);
        }
        int off = (n << 8) + ((kchunk ^ (n & 7)) << 4);
        *reinterpret_cast<uint4*>(blob + off)         = make_uint4(qh[0], qh[1], qh[2], qh[3]);
        *reinterpret_cast<uint4*>(blob + 32768 + off) = make_uint4(ql[0], ql[1], ql[2], ql[3]);
    }
}

__global__ void ksetup(const float* __restrict__ x)
{
    __shared__ float r0[256], r1[256], r2[256];
    __shared__ float mean[3];
    int t = threadIdx.x;
    float s0 = 0.f, s1 = 0.f, s2 = 0.f;
    for (int n = t; n < NN; n += 256) {
        s0 += x[n * 3]; s1 += x[n * 3 + 1]; s2 += x[n * 3 + 2];
    }
    r0[t] = s0; r1[t] = s1; r2[t] = s2;
    __syncthreads();
    for (int s = 128; s > 0; s >>= 1) {
        if (t < s) { r0[t] += r0[t + s]; r1[t] += r1[t + s]; r2[t] += r2[t + s]; }
        __syncthreads();
    }
    if (t == 0) { mean[0] = r0[0] / NN; mean[1] = r1[0] / NN; mean[2] = r2[0] / NN; }
    __syncthreads();
    for (int n = t; n < NN; n += 256)
#pragma unroll
        for (int c = 0; c < 3; c++) {
            float v = x[n * 3 + c] - mean[c];
            g_vec[n * 3 + c] = v; g_vec0[n * 3 + c] = v;
        }
}

__global__ void knode0(const float* __restrict__ h,
                       const float* __restrict__ Wh0, const float* __restrict__ bh0,
                       const float* __restrict__ We0, const float* __restrict__ be0)
{
    __shared__ float hrow[16];
    __shared__ float hfs[FD];
    int i = blockIdx.x, c = threadIdx.x;
    if (c < 16) hrow[c] = h[i * 16 + c];
    __syncthreads();
    float acc = bh0[c];
#pragma unroll
    for (int k = 0; k < 16; k++) acc += hrow[k] * Wh0[k * FD + c];
    g_hf[i * FD + c] = acc;
    hfs[c] = acc;
    __syncthreads();
    float s1 = 0.f, s2 = be0[c];
#pragma unroll 8
    for (int k = 0; k < FD; k++) {
        float hv = hfs[k];
        s1 += hv * We0[(1 + k) * FD + c];
        s2 += hv * We0[(129 + k) * FD + c];
    }
    g_hs[i * FD + c] = s1;
    g_hr[i * FD + c] = s2;
}

__global__ void knode(const float* __restrict__ Wp0, const float* __restrict__ bp0,
                      const float* __restrict__ Wp1, const float* __restrict__ bp1,
                      const float* __restrict__ Wpl, const float* __restrict__ bpl,
                      const float* __restrict__ We0n, const float* __restrict__ be0n,
                      int doNext)
{
    __shared__ float in0[2 * FD], t0s[FD], t1s[FD];
    int i = blockIdx.x, c = threadIdx.x;
    if (c < 3) g_vec[i * 3 + c] += g_vac[i * 3 + c];
    in0[c] = g_magg[i * FD + c];
    float hf = g_hf[i * FD + c];
    in0[FD + c] = hf;
    __syncthreads();
    float a = bp0[c];
#pragma unroll 8
    for (int k = 0; k < 2 * FD; k++) a += in0[k] * Wp0[k * FD + c];
    t0s[c] = siluf(a);
    __syncthreads();
    float b = bp1[c];
#pragma unroll 8
    for (int k = 0; k < FD; k++) b += t0s[k] * Wp1[k * FD + c];
    t1s[c] = b;
    __syncthreads();
    float d = bpl[c];
#pragma unroll 8
    for (int k = 0; k < FD; k++) d += t1s[k] * Wpl[k * FD + c];
    float nhf = hf + d;
    g_hf[i * FD + c] = nhf;
    if (doNext) {
        t0s[c] = nhf;
        __syncthreads();
        float s1 = 0.f, s2 = be0n[c];
#pragma unroll 8
        for (int k = 0; k < FD; k++) {
            float hv = t0s[k];
            s1 += hv * We0n[(1 + k) * FD + c];
            s2 += hv * We0n[(129 + k) * FD + c];
        }
        g_hs[i * FD + c] = s1;
        g_hr[i * FD + c] = s2;
    }
}

__global__ void kout(const float* __restrict__ Wv,
                     const float* __restrict__ Wr, const float* __restrict__ br,
                     float* __restrict__ out)
{
    __shared__ float red[FD], p[FD];
    int i = blockIdx.x, c = threadIdx.x;
    float hf = g_hf[i * FD + c];
    red[c] = hf;
    __syncthreads();
    for (int s = 64; s > 0; s >>= 1) {
        if (c < s) red[c] = fmaxf(red[c], red[c + s]);
        __syncthreads();
    }
    float mx = red[0];
    __syncthreads();
    float ex = __expf(hf - mx);
    red[c] = ex;
    __syncthreads();
    for (int s = 64; s > 0; s >>= 1) {
        if (c < s) red[c] += red[c + s];
        __syncthreads();
    }
    float inv = 1.f / red[0];
    __syncthreads();
    p[c] = ex * inv;
    __syncthreads();
    if (c < 32) {
        float a = br[c];
#pragma unroll 8
        for (int k = 0; k < FD; k++) a += p[k] * Wr[k * 32 + c];
        out[NN * 6 + i * 32 + c] = a;
    }
    if (c < 6) {
        int o = c / 3, cc = c % 3;
        out[i * 6 + c] = (g_vec[i * 3 + cc] - g_vec0[i * 3 + cc]) * Wv[o];
    }
}

extern "C" void kernel_launch(void* const* d_in, const int* in_sizes, int n_in,
                              void* d_out, int out_size)
{
    const float* x   = (const float*)d_in[0];
    const float* h   = (const float*)d_in[1];
    const int* snd   = (const int*)  d_in[2];
    const float* Wh0 = (const float*)d_in[4];
    const float* bh0 = (const float*)d_in[5];
    const float* We0 = (const float*)d_in[6];
    const float* be0 = (const float*)d_in[7];
    const float* We1 = (const float*)d_in[8];
    const float* be1 = (const float*)d_in[9];
    const float* We2 = (const float*)d_in[10];
    const float* be2 = (const float*)d_in[11];
    const float* Winf= (const float*)d_in[12];
    const float* binf= (const float*)d_in[13];
    const float* Wx0 = (const float*)d_in[14];
    const float* bx0 = (const float*)d_in[15];
    const float* Wx1 = (const float*)d_in[16];
    const float* bx1 = (const float*)d_in[17];
    const float* Wxo = (const float*)d_in[18];
    const float* bxo = (const float*)d_in[19];
    const float* Wp0 = (const float*)d_in[20];
    const float* bp0 = (const float*)d_in[21];
    const float* Wp1 = (const float*)d_in[22];
    const float* bp1 = (const float*)d_in[23];
    const float* Wpl = (const float*)d_in[24];
    const float* bpl = (const float*)d_in[25];
    const float* Wv  = (const float*)d_in[26];
    const float* Wr  = (const float*)d_in[27];
    const float* br  = (const float*)d_in[28];
    float* out = (float*)d_out;

    int smem = (int)sizeof(ES);
    cudaFuncSetAttribute(kedge, cudaFuncAttributeMaxDynamicSharedMemorySize, smem);

    const int WB = FD * FD, W0B = 257 * FD, WP0 = 2 * FD * FD;

    ksetup<<<1, 256>>>(x);
    knode0<<<NN, FD>>>(h, Wh0, bh0, We0, be0);
    kwprep<<<8, 256>>>(We1, We2, Wx0, Wx1);

    for (int b = 0; b < 2; b++) {
        kedge<<<NN, NTHR, smem>>>(snd, We0 + b * W0B,
            be1 + b * FD, be2 + b * FD, Winf + b * FD, binf + b,
            bx0 + b * FD, bx1 + b * FD, Wxo + b * FD, bxo + b, b);
        knode<<<NN, FD>>>(Wp0 + b * WP0, bp0 + b * FD,
                          Wp1 + b * WB, bp1 + b * FD,
                          Wpl + b * WB, bpl + b * FD,
                          We0 + W0B, be0 + FD, b == 0 ? 1 : 0);
    }
    kout<<<NN, FD>>>(Wv, Wr, br, out);
}

// round 12
// speedup vs baseline: 1.5790x; 1.5790x over previous
#include <cuda_runtime.h>
#include <cuda_bf16.h>
#include <math.h>

#define NN    512
#define EPN   511
#define FD    128
#define TILE  64
#define NTILE 8
#define NTHR  256

__device__ float g_vec0[NN * 3];
__device__ float g_vec [NN * 3];
__device__ float g_hf  [NN * FD];
__device__ float g_hs  [NN * FD];
__device__ float g_hr  [NN * FD];
__device__ float g_magg[NN * FD];
__device__ float g_vac [NN * 3];
// 8 matrices (2 blocks x {We1,We2,Wx0,Wx1}) as T[n][k] images, 64KB each: [hi|lo]
__device__ __align__(16) __nv_bfloat16 g_wb[8 * 32768];

__device__ __forceinline__ float siluf(float x) {
    return __fdividef(x, 1.f + __expf(-x));
}
__device__ __forceinline__ float sigmf(float x) {
    return __fdividef(1.f, 1.f + __expf(-x));
}

__device__ __forceinline__ unsigned smem_u32(const void* p) {
    unsigned a;
    asm("{ .reg .u64 t; cvta.to.shared.u64 t, %1; cvt.u32.u64 %0, t; }" : "=r"(a) : "l"(p));
    return a;
}
__device__ __forceinline__ void cpasync16(unsigned d, const void* g) {
    asm volatile("cp.async.cg.shared.global [%0], [%1], 16;" :: "r"(d), "l"(g));
}
#define CP_COMMIT() asm volatile("cp.async.commit_group;" ::: "memory")
#define CP_WAIT0()  asm volatile("cp.async.wait_group 0;"  ::: "memory")

__device__ __forceinline__ void ldsm4(unsigned* r, unsigned a) {
    asm volatile("ldmatrix.sync.aligned.m8n8.x4.shared.b16 {%0,%1,%2,%3}, [%4];"
        : "=r"(r[0]), "=r"(r[1]), "=r"(r[2]), "=r"(r[3]) : "r"(a));
}
__device__ __forceinline__ void mma16816(float* c, const unsigned* a,
                                         unsigned b0, unsigned b1) {
    asm volatile("mma.sync.aligned.m16n8k16.row.col.f32.bf16.bf16.f32 "
        "{%0,%1,%2,%3}, {%4,%5,%6,%7}, {%8,%9}, {%0,%1,%2,%3};"
        : "+f"(c[0]), "+f"(c[1]), "+f"(c[2]), "+f"(c[3])
        : "r"(a[0]), "r"(a[1]), "r"(a[2]), "r"(a[3]), "r"(b0), "r"(b1));
}

// image layout: row-major [row][k], 256B rows, 16B chunks XOR-swizzled by row&7
__device__ __forceinline__ int img_off(int e, int c) {
    return (e << 8) + ((((c >> 3) ^ (e & 7))) << 4) + ((c & 7) << 1);
}
__device__ __forceinline__ void st_split2(char* hb, char* lb, int off,
                                          float v0, float v1) {
    __nv_bfloat16 h0 = __float2bfloat16(v0), h1 = __float2bfloat16(v1);
    __nv_bfloat16 l0 = __float2bfloat16(v0 - __bfloat162float(h0));
    __nv_bfloat16 l1 = __float2bfloat16(v1 - __bfloat162float(h1));
    *reinterpret_cast<unsigned*>(hb + off) =
        (unsigned)__bfloat16_as_ushort(h0) | ((unsigned)__bfloat16_as_ushort(h1) << 16);
    *reinterpret_cast<unsigned*>(lb + off) =
        (unsigned)__bfloat16_as_ushort(l0) | ((unsigned)__bfloat16_as_ushort(l1) << 16);
}

struct __align__(16) ES {
    char xhi[16384]; char xlo[16384];   // act0 / m images [e][k], 64 rows
    char yhi[16384]; char ylo[16384];   // GEMM1/3 output images
    char bbuf[32768];                   // ONE weight term (hi or lo), T[n][k]
    float dv[3 * TILE], len[TILE], l2[TILE], gate[TILE], pxs[TILE];
    float gpart[4 * TILE];
    float w0[FD], hrb[FD], winf[FD], wxo[FD];
    float bb1[FD], bb2[FD], bbx0[FD], bbx1[FD];
    float maggs[2 * FD], vred[3 * TILE], vaccs[4], rvec[3];
    int   sidx[TILE];
};

__device__ __forceinline__ void loadB32(char* dst, const __nv_bfloat16* blob, int t) {
    unsigned sd = smem_u32(dst);
    const float4* src = reinterpret_cast<const float4*>(blob);
#pragma unroll
    for (int q = 0; q < 8; q++) { int u = t + q * NTHR; cpasync16(sd + u * 16, src + u); }
    CP_COMMIT();
}

// C[64e][128c] = split3( A @ W ); 8 warps, each a 32e x 32c tile.
// pass1: (Ahi,Alo) x W_hi (resident); swap in W_lo; pass2: Ahi x W_lo.
// epilogue: +bias (opt silu / dot / store split); next W_hi streamed under it.
template <bool ACT, bool DOT, bool STORE>
__device__ __forceinline__ void gemm_tc(ES* S, const char* Ahi, const char* Alo,
                                        const __nv_bfloat16* wlo,
                                        const __nv_bfloat16* wnext_hi,
                                        const float* bias, const float* dw,
                                        char* Ohi, char* Olo, int t)
{
    const int w = t >> 5, lane = t & 31;
    const int e0 = (w >> 2) * 32, c0 = (w & 3) * 32;
    const unsigned l7 = lane & 7;
    float acc[2][4][4];
#pragma unroll
    for (int mt = 0; mt < 2; mt++)
#pragma unroll
        for (int nt = 0; nt < 4; nt++)
#pragma unroll
            for (int q = 0; q < 4; q++) acc[mt][nt][q] = 0.f;

    const unsigned arow = e0 + (lane & 15);
    const unsigned acb  = lane >> 4;
    const unsigned brow = c0 + ((lane >> 4) << 3) + l7;
    const unsigned bcb  = (lane >> 3) & 1;
    const unsigned abh = smem_u32(Ahi) + arow * 256;
    const unsigned abl = smem_u32(Alo) + arow * 256;
    const unsigned bb  = smem_u32(S->bbuf) + brow * 256;

    // ---- pass 1: B = W_hi; both A terms share the B fragments ----
#pragma unroll
    for (int ks = 0; ks < 8; ks++) {
        unsigned ach = (((unsigned)(ks << 1)) | acb) ^ l7;
        unsigned bch = (((unsigned)(ks << 1)) | bcb) ^ l7;
        unsigned ah0[4], ah1[4], al0[4], al1[4];
        ldsm4(ah0, abh + (ach << 4));
        ldsm4(ah1, abh + 16 * 256 + (ach << 4));
        ldsm4(al0, abl + (ach << 4));
        ldsm4(al1, abl + 16 * 256 + (ach << 4));
#pragma unroll
        for (int p = 0; p < 2; p++) {
            unsigned b[4];
            ldsm4(b, bb + p * 16 * 256 + (bch << 4));
            mma16816(acc[0][2 * p],     ah0, b[0], b[1]);
            mma16816(acc[0][2 * p + 1], ah0, b[2], b[3]);
            mma16816(acc[1][2 * p],     ah1, b[0], b[1]);
            mma16816(acc[1][2 * p + 1], ah1, b[2], b[3]);
            mma16816(acc[0][2 * p],     al0, b[0], b[1]);
            mma16816(acc[0][2 * p + 1], al0, b[2], b[3]);
            mma16816(acc[1][2 * p],     al1, b[0], b[1]);
            mma16816(acc[1][2 * p + 1], al1, b[2], b[3]);
        }
    }
    __syncthreads();                 // all warps done reading W_hi
    loadB32(S->bbuf, wlo, t);        // swap in W_lo
    CP_WAIT0();
    __syncthreads();

    // ---- pass 2: B = W_lo; A = hi only ----
#pragma unroll
    for (int ks = 0; ks < 8; ks++) {
        unsigned ach = (((unsigned)(ks << 1)) | acb) ^ l7;
        unsigned bch = (((unsigned)(ks << 1)) | bcb) ^ l7;
        unsigned ah0[4], ah1[4];
        ldsm4(ah0, abh + (ach << 4));
        ldsm4(ah1, abh + 16 * 256 + (ach << 4));
#pragma unroll
        for (int p = 0; p < 2; p++) {
            unsigned b[4];
            ldsm4(b, bb + p * 16 * 256 + (bch << 4));
            mma16816(acc[0][2 * p],     ah0, b[0], b[1]);
            mma16816(acc[0][2 * p + 1], ah0, b[2], b[3]);
            mma16816(acc[1][2 * p],     ah1, b[0], b[1]);
            mma16816(acc[1][2 * p + 1], ah1, b[2], b[3]);
        }
    }
    __syncthreads();                 // done reading W_lo + A images
    loadB32(S->bbuf, wnext_hi, t);   // next matrix W_hi, overlaps epilogue

    const int r = lane >> 2, n2 = (lane & 3) * 2;
    float drow[2][2] = {{0.f, 0.f}, {0.f, 0.f}};
#pragma unroll
    for (int mt = 0; mt < 2; mt++) {
        int eA = e0 + mt * 16 + r;
#pragma unroll
        for (int nt = 0; nt < 4; nt++) {
            int c = c0 + nt * 8 + n2;
            float b0v = bias[c], b1v = bias[c + 1];
            float v00 = acc[mt][nt][0] + b0v, v01 = acc[mt][nt][1] + b1v;
            float v10 = acc[mt][nt][2] + b0v, v11 = acc[mt][nt][3] + b1v;
            if (ACT) { v00 = siluf(v00); v01 = siluf(v01);
                       v10 = siluf(v10); v11 = siluf(v11); }
            if (DOT) {
                drow[mt][0] += v00 * dw[c] + v01 * dw[c + 1];
                drow[mt][1] += v10 * dw[c] + v11 * dw[c + 1];
            }
            if (STORE) {
                st_split2(Ohi, Olo, img_off(eA, c), v00, v01);
                st_split2(Ohi, Olo, img_off(eA + 8, c), v10, v11);
            }
        }
    }
    if (DOT) {
#pragma unroll
        for (int mt = 0; mt < 2; mt++)
#pragma unroll
            for (int hb = 0; hb < 2; hb++) {
                float v = drow[mt][hb];
                v += __shfl_xor_sync(0xffffffffu, v, 1);
                v += __shfl_xor_sync(0xffffffffu, v, 2);
                if ((lane & 3) == 0)
                    S->gpart[(w & 3) * TILE + e0 + mt * 16 + hb * 8 + r] = v;
            }
    }
}

__global__ void __launch_bounds__(NTHR, 2)
kedge(const int* __restrict__ senders, const float* __restrict__ We0r0,
      const float* __restrict__ be1, const float* __restrict__ be2,
      const float* __restrict__ Winf, const float* __restrict__ binfp,
      const float* __restrict__ bx0, const float* __restrict__ bx1,
      const float* __restrict__ Wxo, const float* __restrict__ bxop, int blk)
{
    extern __shared__ char smraw[];
    ES* S = reinterpret_cast<ES*>(smraw);
    const int t = threadIdx.x, i = blockIdx.x;
    const __nv_bfloat16* wb = g_wb + blk * 4 * 32768;
    // matrix m: hi at wb + m*32768, lo at wb + m*32768 + 16384 (elements)

    if (t < FD) {
        S->w0[t] = We0r0[t]; S->hrb[t] = g_hr[i * FD + t];
        S->winf[t] = Winf[t]; S->wxo[t] = Wxo[t];
        S->bb1[t] = be1[t]; S->bb2[t] = be2[t];
        S->bbx0[t] = bx0[t]; S->bbx1[t] = bx1[t];
    }
    if (t < 4) S->vaccs[t] = 0.f;
    if (t < 3) S->rvec[t] = g_vec[i * 3 + t];
    const float binf_s = binfp[0], bxo_s = bxop[0];

    loadB32(S->bbuf, wb, t);        // We1 hi
    __syncthreads();

    const int kk = t & 127, hh = t >> 7;   // hh: edge half (0/1) of 64
    float mreg = 0.f;

    for (int tile = 0; tile < NTILE; tile++) {
        if (t < TILE) {                                  // stage 1
            int je = tile * TILE + t;
            bool valid = je < EPN;
            int s = valid ? senders[i * EPN + je] : i;
            S->sidx[t] = s;
            float d0 = 0.f, d1 = 0.f, d2 = 0.f;
            if (valid) {
                d0 = S->rvec[0] - g_vec[s * 3 + 0];
                d1 = S->rvec[1] - g_vec[s * 3 + 1];
                d2 = S->rvec[2] - g_vec[s * 3 + 2];
            }
            S->dv[t * 3] = d0; S->dv[t * 3 + 1] = d1; S->dv[t * 3 + 2] = d2;
            float dot = d0 * d0 + d1 * d1 + d2 * d2 + 1e-20f;
            S->l2[t] = valid ? dot : 0.f;
            S->len[t] = sqrtf(dot);
        }
        __syncthreads();
        {                                                // stage 2: act0 -> X
            int e = t >> 2, kh = t & 3;
            int s = S->sidx[e];
            float l2v = S->l2[e];
            const float* hsr = g_hs + s * FD + kh * 32;
#pragma unroll 8
            for (int j = 0; j < 32; j += 2) {
                int c = kh * 32 + j;
                float v0 = siluf(l2v * S->w0[c]     + hsr[j]     + S->hrb[c]);
                float v1 = siluf(l2v * S->w0[c + 1] + hsr[j + 1] + S->hrb[c + 1]);
                st_split2(S->xhi, S->xlo, img_off(e, c), v0, v1);
            }
        }
        CP_WAIT0();
        __syncthreads();

        // G1: Y = silu(X @ We1 + be1)
        gemm_tc<true, false, true>(S, S->xhi, S->xlo,
                                   wb + 0 * 32768 + 16384, wb + 1 * 32768,
                                   S->bb1, 0, S->yhi, S->ylo, t);
        CP_WAIT0(); __syncthreads();

        // G2: m = Y @ We2 + be2 -> X; dot winf
        gemm_tc<false, true, true>(S, S->yhi, S->ylo,
                                   wb + 1 * 32768 + 16384, wb + 2 * 32768,
                                   S->bb2, S->winf, S->xhi, S->xlo, t);
        CP_WAIT0(); __syncthreads();
        if (t < TILE) {
            bool valid = (tile * TILE + t) < EPN;
            S->gate[t] = valid ? sigmf(binf_s + S->gpart[t] + S->gpart[TILE + t]
                                       + S->gpart[2 * TILE + t] + S->gpart[3 * TILE + t])
                               : 0.f;
        }
        __syncthreads();
        {                                                // magg partial from X (m)
            float acc = 0.f;
#pragma unroll 4
            for (int e = hh * 32; e < hh * 32 + 32; e++) {
                int adr = img_off(e, kk);
                float m = __bfloat162float(*reinterpret_cast<__nv_bfloat16*>(S->xhi + adr))
                        + __bfloat162float(*reinterpret_cast<__nv_bfloat16*>(S->xlo + adr));
                acc += m * S->gate[e];
            }
            mreg += acc;
        }

        // G3: Y = silu(X @ Wx0 + bx0)
        gemm_tc<true, false, true>(S, S->xhi, S->xlo,
                                   wb + 2 * 32768 + 16384, wb + 3 * 32768,
                                   S->bbx0, 0, S->yhi, S->ylo, t);
        CP_WAIT0(); __syncthreads();

        // G4: px partial = silu(Y @ Wx1 + bx1) . wxo  (no store)
        gemm_tc<true, true, false>(S, S->yhi, S->ylo,
                                   wb + 3 * 32768 + 16384, wb + 0 * 32768,
                                   S->bbx1, S->wxo, S->yhi, S->ylo, t);
        __syncthreads();
        if (t < TILE)
            S->pxs[t] = __fdividef(bxo_s + S->gpart[t] + S->gpart[TILE + t]
                                   + S->gpart[2 * TILE + t] + S->gpart[3 * TILE + t],
                                   1.f + S->len[t]);
        __syncthreads();
        if (t < TILE) {                                  // vac partial
            float p = S->pxs[t];
            S->vred[t] = p * S->dv[t * 3];
            S->vred[TILE + t] = p * S->dv[t * 3 + 1];
            S->vred[2 * TILE + t] = p * S->dv[t * 3 + 2];
        }
        __syncthreads();
        if (t < 96) {
            int c = t >> 5, l = t & 31;
            const float* vr = S->vred + c * TILE;
            float v = vr[l] + vr[l + 32];
#pragma unroll
            for (int o = 16; o; o >>= 1) v += __shfl_down_sync(0xffffffffu, v, o);
            if (l == 0) S->vaccs[c] += v;
        }
        __syncthreads();
    }

    S->maggs[hh * FD + kk] = mreg;
    __syncthreads();
    if (t < FD)
        g_magg[i * FD + t] = (S->maggs[t] + S->maggs[FD + t]) * rsqrtf(511.f);
    if (t < 3) g_vac[i * 3 + t] = S->vaccs[t] * (1.f / 511.f);
}

// weights -> T[n][k] bf16 hi/lo swizzled images (one CTA per matrix)
__global__ void __launch_bounds__(256) kwprep(
    const float* __restrict__ We1, const float* __restrict__ We2,
    const float* __restrict__ Wx0, const float* __restrict__ Wx1)
{
    int m = blockIdx.x, b = m >> 2, g = m & 3;
    const float* W = (g == 0 ? We1 : g == 1 ? We2 : g == 2 ? Wx0 : Wx1) + b * FD * FD;
    char* blob = reinterpret_cast<char*>(g_wb + m * 32768);
    int t = threadIdx.x, n = t & 127, kh = t >> 7;
    for (int kc = 0; kc < 8; kc++) {
        int kchunk = kh * 8 + kc;
        unsigned qh[4], ql[4];
#pragma unroll
        for (int u = 0; u < 4; u++) {
            int k = kchunk * 8 + u * 2;
            float x0 = W[k * FD + n], x1 = W[(k + 1) * FD + n];
            __nv_bfloat16 h0 = __float2bfloat16(x0), h1 = __float2bfloat16(x1);
            __nv_bfloat16 l0 = __float2bfloat16(x0 - __bfloat162float(h0));
            __nv_bfloat16 l1 = __float2bfloat16(x1 - __bfloat162float(h1));
            qh[u] = (unsigned)__bfloat16_as_ushort(h0) | ((unsigned)__bfloat16_as_ushort(h1) << 16);
            ql[u] = (unsigned)__bfloat16_as_ushort(l0) | ((unsigned)__bfloat16_as_ushort(l1) << 16);
        }
        int off = (n << 8) + ((kchunk ^ (n & 7)) << 4);
        *reinterpret_cast<uint4*>(blob + off)         = make_uint4(qh[0], qh[1], qh[2], qh[3]);
        *reinterpret_cast<uint4*>(blob + 32768 + off) = make_uint4(ql[0], ql[1], ql[2], ql[3]);
    }
}

__global__ void ksetup(const float* __restrict__ x)
{
    __shared__ float r0[256], r1[256], r2[256];
    __shared__ float mean[3];
    int t = threadIdx.x;
    float s0 = 0.f, s1 = 0.f, s2 = 0.f;
    for (int n = t; n < NN; n += 256) {
        s0 += x[n * 3]; s1 += x[n * 3 + 1]; s2 += x[n * 3 + 2];
    }
    r0[t] = s0; r1[t] = s1; r2[t] = s2;
    __syncthreads();
    for (int s = 128; s > 0; s >>= 1) {
        if (t < s) { r0[t] += r0[t + s]; r1[t] += r1[t + s]; r2[t] += r2[t + s]; }
        __syncthreads();
    }
    if (t == 0) { mean[0] = r0[0] / NN; mean[1] = r1[0] / NN; mean[2] = r2[0] / NN; }
    __syncthreads();
    for (int n = t; n < NN; n += 256)
#pragma unroll
        for (int c = 0; c < 3; c++) {
            float v = x[n * 3 + c] - mean[c];
            g_vec[n * 3 + c] = v; g_vec0[n * 3 + c] = v;
        }
}

__global__ void knode0(const float* __restrict__ h,
                       const float* __restrict__ Wh0, const float* __restrict__ bh0,
                       const float* __restrict__ We0, const float* __restrict__ be0)
{
    __shared__ float hrow[16];
    __shared__ float hfs[FD];
    int i = blockIdx.x, c = threadIdx.x;
    if (c < 16) hrow[c] = h[i * 16 + c];
    __syncthreads();
    float acc = bh0[c];
#pragma unroll
    for (int k = 0; k < 16; k++) acc += hrow[k] * Wh0[k * FD + c];
    g_hf[i * FD + c] = acc;
    hfs[c] = acc;
    __syncthreads();
    float s1 = 0.f, s2 = be0[c];
#pragma unroll 8
    for (int k = 0; k < FD; k++) {
        float hv = hfs[k];
        s1 += hv * We0[(1 + k) * FD + c];
        s2 += hv * We0[(129 + k) * FD + c];
    }
    g_hs[i * FD + c] = s1;
    g_hr[i * FD + c] = s2;
}

__global__ void knode(const float* __restrict__ Wp0, const float* __restrict__ bp0,
                      const float* __restrict__ Wp1, const float* __restrict__ bp1,
                      const float* __restrict__ Wpl, const float* __restrict__ bpl,
                      const float* __restrict__ We0n, const float* __restrict__ be0n,
                      int doNext)
{
    __shared__ float in0[2 * FD], t0s[FD], t1s[FD];
    int i = blockIdx.x, c = threadIdx.x;
    if (c < 3) g_vec[i * 3 + c] += g_vac[i * 3 + c];
    in0[c] = g_magg[i * FD + c];
    float hf = g_hf[i * FD + c];
    in0[FD + c] = hf;
    __syncthreads();
    float a = bp0[c];
#pragma unroll 8
    for (int k = 0; k < 2 * FD; k++) a += in0[k] * Wp0[k * FD + c];
    t0s[c] = siluf(a);
    __syncthreads();
    float b = bp1[c];
#pragma unroll 8
    for (int k = 0; k < FD; k++) b += t0s[k] * Wp1[k * FD + c];
    t1s[c] = b;
    __syncthreads();
    float d = bpl[c];
#pragma unroll 8
    for (int k = 0; k < FD; k++) d += t1s[k] * Wpl[k * FD + c];
    float nhf = hf + d;
    g_hf[i * FD + c] = nhf;
    if (doNext) {
        t0s[c] = nhf;
        __syncthreads();
        float s1 = 0.f, s2 = be0n[c];
#pragma unroll 8
        for (int k = 0; k < FD; k++) {
            float hv = t0s[k];
            s1 += hv * We0n[(1 + k) * FD + c];
            s2 += hv * We0n[(129 + k) * FD + c];
        }
        g_hs[i * FD + c] = s1;
        g_hr[i * FD + c] = s2;
    }
}

__global__ void kout(const float* __restrict__ Wv,
                     const float* __restrict__ Wr, const float* __restrict__ br,
                     float* __restrict__ out)
{
    __shared__ float red[FD], p[FD];
    int i = blockIdx.x, c = threadIdx.x;
    float hf = g_hf[i * FD + c];
    red[c] = hf;
    __syncthreads();
    for (int s = 64; s > 0; s >>= 1) {
        if (c < s) red[c] = fmaxf(red[c], red[c + s]);
        __syncthreads();
    }
    float mx = red[0];
    __syncthreads();
    float ex = __expf(hf - mx);
    red[c] = ex;
    __syncthreads();
    for (int s = 64; s > 0; s >>= 1) {
        if (c < s) red[c] += red[c + s];
        __syncthreads();
    }
    float inv = 1.f / red[0];
    __syncthreads();
    p[c] = ex * inv;
    __syncthreads();
    if (c < 32) {
        float a = br[c];
#pragma unroll 8
        for (int k = 0; k < FD; k++) a += p[k] * Wr[k * 32 + c];
        out[NN * 6 + i * 32 + c] = a;
    }
    if (c < 6) {
        int o = c / 3, cc = c % 3;
        out[i * 6 + c] = (g_vec[i * 3 + cc] - g_vec0[i * 3 + cc]) * Wv[o];
    }
}

extern "C" void kernel_launch(void* const* d_in, const int* in_sizes, int n_in,
                              void* d_out, int out_size)
{
    const float* x   = (const float*)d_in[0];
    const float* h   = (const float*)d_in[1];
    const int* snd   = (const int*)  d_in[2];
    const float* Wh0 = (const float*)d_in[4];
    const float* bh0 = (const float*)d_in[5];
    const float* We0 = (const float*)d_in[6];
    const float* be0 = (const float*)d_in[7];
    const float* We1 = (const float*)d_in[8];
    const float* be1 = (const float*)d_in[9];
    const float* We2 = (const float*)d_in[10];
    const float* be2 = (const float*)d_in[11];
    const float* Winf= (const float*)d_in[12];
    const float* binf= (const float*)d_in[13];
    const float* Wx0 = (const float*)d_in[14];
    const float* bx0 = (const float*)d_in[15];
    const float* Wx1 = (const float*)d_in[16];
    const float* bx1 = (const float*)d_in[17];
    const float* Wxo = (const float*)d_in[18];
    const float* bxo = (const float*)d_in[19];
    const float* Wp0 = (const float*)d_in[20];
    const float* bp0 = (const float*)d_in[21];
    const float* Wp1 = (const float*)d_in[22];
    const float* bp1 = (const float*)d_in[23];
    const float* Wpl = (const float*)d_in[24];
    const float* bpl = (const float*)d_in[25];
    const float* Wv  = (const float*)d_in[26];
    const float* Wr  = (const float*)d_in[27];
    const float* br  = (const float*)d_in[28];
    float* out = (float*)d_out;

    int smem = (int)sizeof(ES);
    cudaFuncSetAttribute(kedge, cudaFuncAttributeMaxDynamicSharedMemorySize, smem);

    const int WB = FD * FD, W0B = 257 * FD, WP0 = 2 * FD * FD;

    ksetup<<<1, 256>>>(x);
    knode0<<<NN, FD>>>(h, Wh0, bh0, We0, be0);
    kwprep<<<8, 256>>>(We1, We2, Wx0, Wx1);

    for (int b = 0; b < 2; b++) {
        kedge<<<NN, NTHR, smem>>>(snd, We0 + b * W0B,
            be1 + b * FD, be2 + b * FD, Winf + b * FD, binf + b,
            bx0 + b * FD, bx1 + b * FD, Wxo + b * FD, bxo + b, b);
        knode<<<NN, FD>>>(Wp0 + b * WP0, bp0 + b * FD,
                          Wp1 + b * WB, bp1 + b * FD,
                          Wpl + b * WB, bpl + b * FD,
                          We0 + W0B, be0 + FD, b == 0 ? 1 : 0);
    }
    kout<<<NN, FD>>>(Wv, Wr, br, out);
}

// round 13
// speedup vs baseline: 1.5920x; 1.0082x over previous
#include <cuda_runtime.h>
#include <cuda_bf16.h>
#include <math.h>

#define NN    512
#define EPN   511
#define FD    128
#define TILE  64
#define NTILE 8
#define NTHR  256

__device__ float g_vec0[NN * 3];
__device__ float g_vec [NN * 3];
__device__ float g_hf  [NN * FD];
__device__ float g_hs  [NN * FD];
__device__ float g_hr  [NN * FD];
__device__ float g_magg[NN * FD];
__device__ float g_vac [NN * 3];
// 8 matrices (2 blocks x {We1,We2,Wx0,Wx1}) as T[n][k] images, 64KB each: [hi|lo]
__device__ __align__(16) __nv_bfloat16 g_wb[8 * 32768];

__device__ __forceinline__ float siluf(float x) {
    return __fdividef(x, 1.f + __expf(-x));
}
__device__ __forceinline__ float sigmf(float x) {
    return __fdividef(1.f, 1.f + __expf(-x));
}

__device__ __forceinline__ unsigned smem_u32(const void* p) {
    unsigned a;
    asm("{ .reg .u64 t; cvta.to.shared.u64 t, %1; cvt.u32.u64 %0, t; }" : "=r"(a) : "l"(p));
    return a;
}
__device__ __forceinline__ void cpasync16(unsigned d, const void* g) {
    asm volatile("cp.async.cg.shared.global [%0], [%1], 16;" :: "r"(d), "l"(g));
}
#define CP_COMMIT() asm volatile("cp.async.commit_group;" ::: "memory")
#define CP_WAIT0()  asm volatile("cp.async.wait_group 0;"  ::: "memory")
#define BAR_PAIR(id) asm volatile("bar.sync %0, 64;" :: "r"(id) : "memory")

__device__ __forceinline__ void ldsm4(unsigned* r, unsigned a) {
    asm volatile("ldmatrix.sync.aligned.m8n8.x4.shared.b16 {%0,%1,%2,%3}, [%4];"
        : "=r"(r[0]), "=r"(r[1]), "=r"(r[2]), "=r"(r[3]) : "r"(a));
}
__device__ __forceinline__ void mma16816(float* c, const unsigned* a,
                                         unsigned b0, unsigned b1) {
    asm volatile("mma.sync.aligned.m16n8k16.row.col.f32.bf16.bf16.f32 "
        "{%0,%1,%2,%3}, {%4,%5,%6,%7}, {%8,%9}, {%0,%1,%2,%3};"
        : "+f"(c[0]), "+f"(c[1]), "+f"(c[2]), "+f"(c[3])
        : "r"(a[0]), "r"(a[1]), "r"(a[2]), "r"(a[3]), "r"(b0), "r"(b1));
}

// image layout: row-major [row][k], 256B rows, 16B chunks XOR-swizzled by row&7
__device__ __forceinline__ int img_off(int e, int c) {
    return (e << 8) + ((((c >> 3) ^ (e & 7))) << 4) + ((c & 7) << 1);
}
__device__ __forceinline__ void st_split2(char* hb, char* lb, int off,
                                          float v0, float v1) {
    __nv_bfloat16 h0 = __float2bfloat16(v0), h1 = __float2bfloat16(v1);
    __nv_bfloat16 l0 = __float2bfloat16(v0 - __bfloat162float(h0));
    __nv_bfloat16 l1 = __float2bfloat16(v1 - __bfloat162float(h1));
    *reinterpret_cast<unsigned*>(hb + off) =
        (unsigned)__bfloat16_as_ushort(h0) | ((unsigned)__bfloat16_as_ushort(h1) << 16);
    *reinterpret_cast<unsigned*>(lb + off) =
        (unsigned)__bfloat16_as_ushort(l0) | ((unsigned)__bfloat16_as_ushort(l1) << 16);
}

struct __align__(16) ES {
    char xhi[16384]; char xlo[16384];   // act0 / m images [e][k], 64 rows
    char yhi[16384]; char ylo[16384];   // GEMM1/3 output images
    char bbuf[32768];                   // weight term; 4 x 8KB pair regions
    float dv[3 * TILE], len[TILE], l2[TILE], gate[TILE], pxs[TILE];
    float gpart[4 * TILE];
    float w0[FD], hrb[FD], winf[FD], wxo[FD];
    float bb1[FD], bb2[FD], bbx0[FD], bbx1[FD];
    float maggs[2 * FD], vred[3 * TILE], vaccs[4], rvec[3];
    int   sidx[TILE];
};

// pair (64 threads, pl=0..63) loads its 8KB region: rows [32g, 32g+32) of one term
__device__ __forceinline__ void loadBpair(char* dstreg, const __nv_bfloat16* srcreg,
                                          int pl) {
    unsigned sd = smem_u32(dstreg);
    const float4* s4 = reinterpret_cast<const float4*>(srcreg);
#pragma unroll
    for (int q = 0; q < 8; q++) { int u = pl + q * 64; cpasync16(sd + u * 16, s4 + u); }
    CP_COMMIT();
}

// C[64e][128c] = split3( A @ W ); 8 warps, each a 32e x 32c tile.
// Weight staging is PAIR-SCOPED: pair {g, g+4} owns bbuf rows [32g,32g+32) and
// swaps hi->lo->next_hi with bar.sync(g+1,64) — no full-CTA weight barriers.
// On entry, the pair's W_hi cp.async (issued by previous gemm) is awaited here.
template <bool ACT, bool DOT, bool STORE>
__device__ __forceinline__ void gemm_tc(ES* S, const char* Ahi, const char* Alo,
                                        const __nv_bfloat16* wcur,
                                        const __nv_bfloat16* wnext,
                                        const float* bias, const float* dw,
                                        char* Ohi, char* Olo, int t)
{
    const int w = t >> 5, lane = t & 31;
    const int g = w & 3;
    const int e0 = (w >> 2) * 32, c0 = g * 32;
    const int pl = ((w >> 2) << 5) | lane;
    char* breg = S->bbuf + g * 8192;
    const unsigned l7 = lane & 7;
    float acc[2][4][4];
#pragma unroll
    for (int mt = 0; mt < 2; mt++)
#pragma unroll
        for (int nt = 0; nt < 4; nt++)
#pragma unroll
            for (int q = 0; q < 4; q++) acc[mt][nt][q] = 0.f;

    const unsigned arow = e0 + (lane & 15);
    const unsigned acb  = lane >> 4;
    // brow relative to pair region: local rows 0..31
    const unsigned browl = ((lane >> 4) << 3) + l7;
    const unsigned bcb  = (lane >> 3) & 1;
    const unsigned abh = smem_u32(Ahi) + arow * 256;
    const unsigned abl = smem_u32(Alo) + arow * 256;
    const unsigned bb  = smem_u32(breg) + browl * 256;

    CP_WAIT0();                      // W_hi region (issued by prev gemm) arrived
    BAR_PAIR(g + 1);                 // visible to both warps of the pair

    // ---- pass 1: B = W_hi; both A terms share the B fragments ----
#pragma unroll
    for (int ks = 0; ks < 8; ks++) {
        unsigned ach = (((unsigned)(ks << 1)) | acb) ^ l7;
        unsigned bch = (((unsigned)(ks << 1)) | bcb) ^ l7;
        unsigned ah0[4], ah1[4], al0[4], al1[4];
        ldsm4(ah0, abh + (ach << 4));
        ldsm4(ah1, abh + 16 * 256 + (ach << 4));
        ldsm4(al0, abl + (ach << 4));
        ldsm4(al1, abl + 16 * 256 + (ach << 4));
#pragma unroll
        for (int p = 0; p < 2; p++) {
            unsigned b[4];
            ldsm4(b, bb + p * 16 * 256 + (bch << 4));
            mma16816(acc[0][2 * p],     ah0, b[0], b[1]);
            mma16816(acc[0][2 * p + 1], ah0, b[2], b[3]);
            mma16816(acc[1][2 * p],     ah1, b[0], b[1]);
            mma16816(acc[1][2 * p + 1], ah1, b[2], b[3]);
            mma16816(acc[0][2 * p],     al0, b[0], b[1]);
            mma16816(acc[0][2 * p + 1], al0, b[2], b[3]);
            mma16816(acc[1][2 * p],     al1, b[0], b[1]);
            mma16816(acc[1][2 * p + 1], al1, b[2], b[3]);
        }
    }
    BAR_PAIR(g + 1);                         // pair done reading W_hi
    loadBpair(breg, wcur + 16384 + g * 4096, pl);   // swap in W_lo region
    CP_WAIT0();
    BAR_PAIR(g + 1);

    // ---- pass 2: B = W_lo; A = hi only ----
#pragma unroll
    for (int ks = 0; ks < 8; ks++) {
        unsigned ach = (((unsigned)(ks << 1)) | acb) ^ l7;
        unsigned bch = (((unsigned)(ks << 1)) | bcb) ^ l7;
        unsigned ah0[4], ah1[4];
        ldsm4(ah0, abh + (ach << 4));
        ldsm4(ah1, abh + 16 * 256 + (ach << 4));
#pragma unroll
        for (int p = 0; p < 2; p++) {
            unsigned b[4];
            ldsm4(b, bb + p * 16 * 256 + (bch << 4));
            mma16816(acc[0][2 * p],     ah0, b[0], b[1]);
            mma16816(acc[0][2 * p + 1], ah0, b[2], b[3]);
            mma16816(acc[1][2 * p],     ah1, b[0], b[1]);
            mma16816(acc[1][2 * p + 1], ah1, b[2], b[3]);
        }
    }
    BAR_PAIR(g + 1);                         // pair done reading W_lo
    loadBpair(breg, wnext + g * 4096, pl);   // prefetch next matrix W_hi region

    const int r = lane >> 2, n2 = (lane & 3) * 2;
    float drow[2][2] = {{0.f, 0.f}, {0.f, 0.f}};
#pragma unroll
    for (int mt = 0; mt < 2; mt++) {
        int eA = e0 + mt * 16 + r;
#pragma unroll
        for (int nt = 0; nt < 4; nt++) {
            int c = c0 + nt * 8 + n2;
            float b0v = bias[c], b1v = bias[c + 1];
            float v00 = acc[mt][nt][0] + b0v, v01 = acc[mt][nt][1] + b1v;
            float v10 = acc[mt][nt][2] + b0v, v11 = acc[mt][nt][3] + b1v;
            if (ACT) { v00 = siluf(v00); v01 = siluf(v01);
                       v10 = siluf(v10); v11 = siluf(v11); }
            if (DOT) {
                drow[mt][0] += v00 * dw[c] + v01 * dw[c + 1];
                drow[mt][1] += v10 * dw[c] + v11 * dw[c + 1];
            }
            if (STORE) {
                st_split2(Ohi, Olo, img_off(eA, c), v00, v01);
                st_split2(Ohi, Olo, img_off(eA + 8, c), v10, v11);
            }
        }
    }
    if (DOT) {
#pragma unroll
        for (int mt = 0; mt < 2; mt++)
#pragma unroll
            for (int hb = 0; hb < 2; hb++) {
                float v = drow[mt][hb];
                v += __shfl_xor_sync(0xffffffffu, v, 1);
                v += __shfl_xor_sync(0xffffffffu, v, 2);
                if ((lane & 3) == 0)
                    S->gpart[g * TILE + e0 + mt * 16 + hb * 8 + r] = v;
            }
    }
}

__global__ void __launch_bounds__(NTHR, 2)
kedge(const int* __restrict__ senders, const float* __restrict__ We0r0,
      const float* __restrict__ be1, const float* __restrict__ be2,
      const float* __restrict__ Winf, const float* __restrict__ binfp,
      const float* __restrict__ bx0, const float* __restrict__ bx1,
      const float* __restrict__ Wxo, const float* __restrict__ bxop, int blk)
{
    extern __shared__ char smraw[];
    ES* S = reinterpret_cast<ES*>(smraw);
    const int t = threadIdx.x, i = blockIdx.x;
    const int w = t >> 5, lane = t & 31;
    const int g = w & 3;
    const int pl = ((w >> 2) << 5) | lane;
    const __nv_bfloat16* wb = g_wb + blk * 4 * 32768;
    // matrix m: hi at wb + m*32768, lo at wb + m*32768 + 16384 (elements)

    if (t < FD) {
        S->w0[t] = We0r0[t]; S->hrb[t] = g_hr[i * FD + t];
        S->winf[t] = Winf[t]; S->wxo[t] = Wxo[t];
        S->bb1[t] = be1[t]; S->bb2[t] = be2[t];
        S->bbx0[t] = bx0[t]; S->bbx1[t] = bx1[t];
    }
    if (t < 4) S->vaccs[t] = 0.f;
    if (t < 3) S->rvec[t] = g_vec[i * 3 + t];
    const float binf_s = binfp[0], bxo_s = bxop[0];

    loadBpair(S->bbuf + g * 8192, wb + g * 4096, pl);   // We1 hi, pair region
    __syncthreads();

    const int kk = t & 127, hh = t >> 7;   // hh: edge half (0/1) of 64
    float mreg = 0.f;

    for (int tile = 0; tile < NTILE; tile++) {
        if (t < TILE) {                                  // stage 1
            int je = tile * TILE + t;
            bool valid = je < EPN;
            int s = valid ? senders[i * EPN + je] : i;
            S->sidx[t] = s;
            float d0 = 0.f, d1 = 0.f, d2 = 0.f;
            if (valid) {
                d0 = S->rvec[0] - g_vec[s * 3 + 0];
                d1 = S->rvec[1] - g_vec[s * 3 + 1];
                d2 = S->rvec[2] - g_vec[s * 3 + 2];
            }
            S->dv[t * 3] = d0; S->dv[t * 3 + 1] = d1; S->dv[t * 3 + 2] = d2;
            float dot = d0 * d0 + d1 * d1 + d2 * d2 + 1e-20f;
            S->l2[t] = valid ? dot : 0.f;
            S->len[t] = sqrtf(dot);
        }
        __syncthreads();
        {                                                // stage 2: act0 -> X
            int e = t >> 2, kh = t & 3;
            int s = S->sidx[e];
            float l2v = S->l2[e];
            const float* hsr = g_hs + s * FD + kh * 32;
#pragma unroll 8
            for (int j = 0; j < 32; j += 2) {
                int c = kh * 32 + j;
                float v0 = siluf(l2v * S->w0[c]     + hsr[j]     + S->hrb[c]);
                float v1 = siluf(l2v * S->w0[c + 1] + hsr[j + 1] + S->hrb[c + 1]);
                st_split2(S->xhi, S->xlo, img_off(e, c), v0, v1);
            }
        }
        __syncthreads();

        // G1: Y = silu(X @ We1 + be1)
        gemm_tc<true, false, true>(S, S->xhi, S->xlo,
                                   wb + 0 * 32768, wb + 1 * 32768,
                                   S->bb1, 0, S->yhi, S->ylo, t);
        __syncthreads();

        // G2: m = Y @ We2 + be2 -> X; dot winf
        gemm_tc<false, true, true>(S, S->yhi, S->ylo,
                                   wb + 1 * 32768, wb + 2 * 32768,
                                   S->bb2, S->winf, S->xhi, S->xlo, t);
        __syncthreads();
        if (t < TILE) {
            bool valid = (tile * TILE + t) < EPN;
            S->gate[t] = valid ? sigmf(binf_s + S->gpart[t] + S->gpart[TILE + t]
                                       + S->gpart[2 * TILE + t] + S->gpart[3 * TILE + t])
                               : 0.f;
        }
        __syncthreads();
        {                                                // magg partial from X (m)
            float acc = 0.f;
#pragma unroll 4
            for (int e = hh * 32; e < hh * 32 + 32; e++) {
                int adr = img_off(e, kk);
                float m = __bfloat162float(*reinterpret_cast<__nv_bfloat16*>(S->xhi + adr))
                        + __bfloat162float(*reinterpret_cast<__nv_bfloat16*>(S->xlo + adr));
                acc += m * S->gate[e];
            }
            mreg += acc;
        }

        // G3: Y = silu(X @ Wx0 + bx0)
        gemm_tc<true, false, true>(S, S->xhi, S->xlo,
                                   wb + 2 * 32768, wb + 3 * 32768,
                                   S->bbx0, 0, S->yhi, S->ylo, t);
        __syncthreads();

        // G4: px partial = silu(Y @ Wx1 + bx1) . wxo  (no store); next = We1
        gemm_tc<true, true, false>(S, S->yhi, S->ylo,
                                   wb + 3 * 32768, wb + 0 * 32768,
                                   S->bbx1, S->wxo, S->yhi, S->ylo, t);
        __syncthreads();
        if (t < TILE)
            S->pxs[t] = __fdividef(bxo_s + S->gpart[t] + S->gpart[TILE + t]
                                   + S->gpart[2 * TILE + t] + S->gpart[3 * TILE + t],
                                   1.f + S->len[t]);
        __syncthreads();
        if (t < TILE) {                                  // vac partial
            float p = S->pxs[t];
            S->vred[t] = p * S->dv[t * 3];
            S->vred[TILE + t] = p * S->dv[t * 3 + 1];
            S->vred[2 * TILE + t] = p * S->dv[t * 3 + 2];
        }
        __syncthreads();
        if (t < 96) {
            int c = t >> 5, l = t & 31;
            const float* vr = S->vred + c * TILE;
            float v = vr[l] + vr[l + 32];
#pragma unroll
            for (int o = 16; o; o >>= 1) v += __shfl_down_sync(0xffffffffu, v, o);
            if (l == 0) S->vaccs[c] += v;
        }
        __syncthreads();
    }

    S->maggs[hh * FD + kk] = mreg;
    __syncthreads();
    if (t < FD)
        g_magg[i * FD + t] = (S->maggs[t] + S->maggs[FD + t]) * rsqrtf(511.f);
    if (t < 3) g_vac[i * 3 + t] = S->vaccs[t] * (1.f / 511.f);
}

// weights -> T[n][k] bf16 hi/lo swizzled images (one CTA per matrix)
__global__ void __launch_bounds__(256) kwprep(
    const float* __restrict__ We1, const float* __restrict__ We2,
    const float* __restrict__ Wx0, const float* __restrict__ Wx1)
{
    int m = blockIdx.x, b = m >> 2, g = m & 3;
    const float* W = (g == 0 ? We1 : g == 1 ? We2 : g == 2 ? Wx0 : Wx1) + b * FD * FD;
    char* blob = reinterpret_cast<char*>(g_wb + m * 32768);
    int t = threadIdx.x, n = t & 127, kh = t >> 7;
    for (int kc = 0; kc < 8; kc++) {
        int kchunk = kh * 8 + kc;
        unsigned qh[4], ql[4];
#pragma unroll
        for (int u = 0; u < 4; u++) {
            int k = kchunk * 8 + u * 2;
            float x0 = W[k * FD + n], x1 = W[(k + 1) * FD + n];
            __nv_bfloat16 h0 = __float2bfloat16(x0), h1 = __float2bfloat16(x1);
            __nv_bfloat16 l0 = __float2bfloat16(x0 - __bfloat162float(h0));
            __nv_bfloat16 l1 = __float2bfloat16(x1 - __bfloat162float(h1));
            qh[u] = (unsigned)__bfloat16_as_ushort(h0) | ((unsigned)__bfloat16_as_ushort(h1) << 16);
            ql[u] = (unsigned)__bfloat16_as_ushort(l0) | ((unsigned)__bfloat16_as_ushort(l1) << 16);
        }
        int off = (n << 8) + ((kchunk ^ (n & 7)) << 4);
        *reinterpret_cast<uint4*>(blob + off)         = make_uint4(qh[0], qh[1], qh[2], qh[3]);
        *reinterpret_cast<uint4*>(blob + 32768 + off) = make_uint4(ql[0], ql[1], ql[2], ql[3]);
    }
}

__global__ void ksetup(const float* __restrict__ x)
{
    __shared__ float r0[256], r1[256], r2[256];
    __shared__ float mean[3];
    int t = threadIdx.x;
    float s0 = 0.f, s1 = 0.f, s2 = 0.f;
    for (int n = t; n < NN; n += 256) {
        s0 += x[n * 3]; s1 += x[n * 3 + 1]; s2 += x[n * 3 + 2];
    }
    r0[t] = s0; r1[t] = s1; r2[t] = s2;
    __syncthreads();
    for (int s = 128; s > 0; s >>= 1) {
        if (t < s) { r0[t] += r0[t + s]; r1[t] += r1[t + s]; r2[t] += r2[t + s]; }
        __syncthreads();
    }
    if (t == 0) { mean[0] = r0[0] / NN; mean[1] = r1[0] / NN; mean[2] = r2[0] / NN; }
    __syncthreads();
    for (int n = t; n < NN; n += 256)
#pragma unroll
        for (int c = 0; c < 3; c++) {
            float v = x[n * 3 + c] - mean[c];
            g_vec[n * 3 + c] = v; g_vec0[n * 3 + c] = v;
        }
}

__global__ void knode0(const float* __restrict__ h,
                       const float* __restrict__ Wh0, const float* __restrict__ bh0,
                       const float* __restrict__ We0, const float* __restrict__ be0)
{
    __shared__ float hrow[16];
    __shared__ float hfs[FD];
    int i = blockIdx.x, c = threadIdx.x;
    if (c < 16) hrow[c] = h[i * 16 + c];
    __syncthreads();
    float acc = bh0[c];
#pragma unroll
    for (int k = 0; k < 16; k++) acc += hrow[k] * Wh0[k * FD + c];
    g_hf[i * FD + c] = acc;
    hfs[c] = acc;
    __syncthreads();
    float s1 = 0.f, s2 = be0[c];
#pragma unroll 8
    for (int k = 0; k < FD; k++) {
        float hv = hfs[k];
        s1 += hv * We0[(1 + k) * FD + c];
        s2 += hv * We0[(129 + k) * FD + c];
    }
    g_hs[i * FD + c] = s1;
    g_hr[i * FD + c] = s2;
}

__global__ void knode(const float* __restrict__ Wp0, const float* __restrict__ bp0,
                      const float* __restrict__ Wp1, const float* __restrict__ bp1,
                      const float* __restrict__ Wpl, const float* __restrict__ bpl,
                      const float* __restrict__ We0n, const float* __restrict__ be0n,
                      int doNext)
{
    __shared__ float in0[2 * FD], t0s[FD], t1s[FD];
    int i = blockIdx.x, c = threadIdx.x;
    if (c < 3) g_vec[i * 3 + c] += g_vac[i * 3 + c];
    in0[c] = g_magg[i * FD + c];
    float hf = g_hf[i * FD + c];
    in0[FD + c] = hf;
    __syncthreads();
    float a = bp0[c];
#pragma unroll 8
    for (int k = 0; k < 2 * FD; k++) a += in0[k] * Wp0[k * FD + c];
    t0s[c] = siluf(a);
    __syncthreads();
    float b = bp1[c];
#pragma unroll 8
    for (int k = 0; k < FD; k++) b += t0s[k] * Wp1[k * FD + c];
    t1s[c] = b;
    __syncthreads();
    float d = bpl[c];
#pragma unroll 8
    for (int k = 0; k < FD; k++) d += t1s[k] * Wpl[k * FD + c];
    float nhf = hf + d;
    g_hf[i * FD + c] = nhf;
    if (doNext) {
        t0s[c] = nhf;
        __syncthreads();
        float s1 = 0.f, s2 = be0n[c];
#pragma unroll 8
        for (int k = 0; k < FD; k++) {
            float hv = t0s[k];
            s1 += hv * We0n[(1 + k) * FD + c];
            s2 += hv * We0n[(129 + k) * FD + c];
        }
        g_hs[i * FD + c] = s1;
        g_hr[i * FD + c] = s2;
    }
}

__global__ void kout(const float* __restrict__ Wv,
                     const float* __restrict__ Wr, const float* __restrict__ br,
                     float* __restrict__ out)
{
    __shared__ float red[FD], p[FD];
    int i = blockIdx.x, c = threadIdx.x;
    float hf = g_hf[i * FD + c];
    red[c] = hf;
    __syncthreads();
    for (int s = 64; s > 0; s >>= 1) {
        if (c < s) red[c] = fmaxf(red[c], red[c + s]);
        __syncthreads();
    }
    float mx = red[0];
    __syncthreads();
    float ex = __expf(hf - mx);
    red[c] = ex;
    __syncthreads();
    for (int s = 64; s > 0; s >>= 1) {
        if (c < s) red[c] += red[c + s];
        __syncthreads();
    }
    float inv = 1.f / red[0];
    __syncthreads();
    p[c] = ex * inv;
    __syncthreads();
    if (c < 32) {
        float a = br[c];
#pragma unroll 8
        for (int k = 0; k < FD; k++) a += p[k] * Wr[k * 32 + c];
        out[NN * 6 + i * 32 + c] = a;
    }
    if (c < 6) {
        int o = c / 3, cc = c % 3;
        out[i * 6 + c] = (g_vec[i * 3 + cc] - g_vec0[i * 3 + cc]) * Wv[o];
    }
}

extern "C" void kernel_launch(void* const* d_in, const int* in_sizes, int n_in,
                              void* d_out, int out_size)
{
    const float* x   = (const float*)d_in[0];
    const float* h   = (const float*)d_in[1];
    const int* snd   = (const int*)  d_in[2];
    const float* Wh0 = (const float*)d_in[4];
    const float* bh0 = (const float*)d_in[5];
    const float* We0 = (const float*)d_in[6];
    const float* be0 = (const float*)d_in[7];
    const float* We1 = (const float*)d_in[8];
    const float* be1 = (const float*)d_in[9];
    const float* We2 = (const float*)d_in[10];
    const float* be2 = (const float*)d_in[11];
    const float* Winf= (const float*)d_in[12];
    const float* binf= (const float*)d_in[13];
    const float* Wx0 = (const float*)d_in[14];
    const float* bx0 = (const float*)d_in[15];
    const float* Wx1 = (const float*)d_in[16];
    const float* bx1 = (const float*)d_in[17];
    const float* Wxo = (const float*)d_in[18];
    const float* bxo = (const float*)d_in[19];
    const float* Wp0 = (const float*)d_in[20];
    const float* bp0 = (const float*)d_in[21];
    const float* Wp1 = (const float*)d_in[22];
    const float* bp1 = (const float*)d_in[23];
    const float* Wpl = (const float*)d_in[24];
    const float* bpl = (const float*)d_in[25];
    const float* Wv  = (const float*)d_in[26];
    const float* Wr  = (const float*)d_in[27];
    const float* br  = (const float*)d_in[28];
    float* out = (float*)d_out;

    int smem = (int)sizeof(ES);
    cudaFuncSetAttribute(kedge, cudaFuncAttributeMaxDynamicSharedMemorySize, smem);

    const int WB = FD * FD, W0B = 257 * FD, WP0 = 2 * FD * FD;

    ksetup<<<1, 256>>>(x);
    knode0<<<NN, FD>>>(h, Wh0, bh0, We0, be0);
    kwprep<<<8, 256>>>(We1, We2, Wx0, Wx1);

    for (int b = 0; b < 2; b++) {
        kedge<<<NN, NTHR, smem>>>(snd, We0 + b * W0B,
            be1 + b * FD, be2 + b * FD, Winf + b * FD, binf + b,
            bx0 + b * FD, bx1 + b * FD, Wxo + b * FD, bxo + b, b);
        knode<<<NN, FD>>>(Wp0 + b * WP0, bp0 + b * FD,
                          Wp1 + b * WB, bp1 + b * FD,
                          Wpl + b * WB, bpl + b * FD,
                          We0 + W0B, be0 + FD, b == 0 ? 1 : 0);
    }
    kout<<<NN, FD>>>(Wv, Wr, br, out);
}

// round 14
// speedup vs baseline: 1.6159x; 1.0150x over previous
#include <cuda_runtime.h>
#include <cuda_bf16.h>
#include <math.h>

#define NN    512
#define EPN   511
#define FD    128
#define TILE  64
#define NTILE 8
#define NTHR  256

__device__ float g_vec0[NN * 3];
__device__ float g_vec [NN * 3];
__device__ float g_hf  [NN * FD];
__device__ float g_hs  [NN * FD];
__device__ float g_hr  [NN * FD];
__device__ float g_magg[NN * FD];
__device__ float g_vac [NN * 3];
// 8 matrices (2 blocks x {We1,We2,Wx0,Wx1}) as T[n][k] images, 64KB each: [hi|lo]
__device__ __align__(16) __nv_bfloat16 g_wb[8 * 32768];

__device__ __forceinline__ float siluf(float x) {
    return __fdividef(x, 1.f + __expf(-x));
}
__device__ __forceinline__ float sigmf(float x) {
    return __fdividef(1.f, 1.f + __expf(-x));
}

__device__ __forceinline__ unsigned smem_u32(const void* p) {
    unsigned a;
    asm("{ .reg .u64 t; cvta.to.shared.u64 t, %1; cvt.u32.u64 %0, t; }" : "=r"(a) : "l"(p));
    return a;
}
__device__ __forceinline__ void cpasync16(unsigned d, const void* g) {
    asm volatile("cp.async.cg.shared.global [%0], [%1], 16;" :: "r"(d), "l"(g));
}
#define CP_COMMIT() asm volatile("cp.async.commit_group;" ::: "memory")
#define CP_WAIT0()  asm volatile("cp.async.wait_group 0;"  ::: "memory")
#define BAR_PAIR(id) asm volatile("bar.sync %0, 64;" :: "r"(id) : "memory")

__device__ __forceinline__ void ldsm4(unsigned* r, unsigned a) {
    asm volatile("ldmatrix.sync.aligned.m8n8.x4.shared.b16 {%0,%1,%2,%3}, [%4];"
        : "=r"(r[0]), "=r"(r[1]), "=r"(r[2]), "=r"(r[3]) : "r"(a));
}
__device__ __forceinline__ void mma16816(float* c, const unsigned* a,
                                         unsigned b0, unsigned b1) {
    asm volatile("mma.sync.aligned.m16n8k16.row.col.f32.bf16.bf16.f32 "
        "{%0,%1,%2,%3}, {%4,%5,%6,%7}, {%8,%9}, {%0,%1,%2,%3};"
        : "+f"(c[0]), "+f"(c[1]), "+f"(c[2]), "+f"(c[3])
        : "r"(a[0]), "r"(a[1]), "r"(a[2]), "r"(a[3]), "r"(b0), "r"(b1));
}

// image layout: row-major [row][k], 256B rows, 16B chunks XOR-swizzled by row&7
__device__ __forceinline__ int img_off(int e, int c) {
    return (e << 8) + ((((c >> 3) ^ (e & 7))) << 4) + ((c & 7) << 1);
}
__device__ __forceinline__ void st_split2(char* hb, char* lb, int off,
                                          float v0, float v1) {
    __nv_bfloat16 h0 = __float2bfloat16(v0), h1 = __float2bfloat16(v1);
    __nv_bfloat16 l0 = __float2bfloat16(v0 - __bfloat162float(h0));
    __nv_bfloat16 l1 = __float2bfloat16(v1 - __bfloat162float(h1));
    *reinterpret_cast<unsigned*>(hb + off) =
        (unsigned)__bfloat16_as_ushort(h0) | ((unsigned)__bfloat16_as_ushort(h1) << 16);
    *reinterpret_cast<unsigned*>(lb + off) =
        (unsigned)__bfloat16_as_ushort(l0) | ((unsigned)__bfloat16_as_ushort(l1) << 16);
}

struct __align__(16) ES {
    char xhi[16384]; char xlo[16384];   // act0 / m images [e][k], 64 rows
    char yhi[16384]; char ylo[16384];   // GEMM1/3 output images
    char bbuf[32768];                   // weight term; 4 x 8KB pair regions
    float dv[3 * TILE], len[TILE], l2[TILE], gate[TILE], pxs[TILE];
    float gpart[4 * TILE];
    float w0[FD], hrb[FD], winf[FD], wxo[FD];
    float bb1[FD], bb2[FD], bbx0[FD], bbx1[FD];
    float maggs[2 * FD], vred[3 * TILE], vaccs[4], rvec[3];
    int   sidx[TILE];
};

// pair (64 threads, pl=0..63) loads its 8KB region: rows [32g, 32g+32) of one term
__device__ __forceinline__ void loadBpair(char* dstreg, const __nv_bfloat16* srcreg,
                                          int pl) {
    unsigned sd = smem_u32(dstreg);
    const float4* s4 = reinterpret_cast<const float4*>(srcreg);
#pragma unroll
    for (int q = 0; q < 8; q++) { int u = pl + q * 64; cpasync16(sd + u * 16, s4 + u); }
    CP_COMMIT();
}

// C[64e][128c] = split3( A @ W ); 8 warps, each a 32e x 32c tile.
// Weight staging is PAIR-SCOPED (bbuf rows [32g,32g+32) per pair {g,g+4}).
// MAGG variant (used for G2): after the DOT epilogue, computes gate in-CTA and
// folds the magg reduction directly from the live acc registers (no image read).
template <bool ACT, bool DOT, bool STORE, bool MAGG = false>
__device__ __forceinline__ void gemm_tc(ES* S, const char* Ahi, const char* Alo,
                                        const __nv_bfloat16* wcur,
                                        const __nv_bfloat16* wnext,
                                        const float* bias, const float* dw,
                                        char* Ohi, char* Olo, int t,
                                        float binf_s = 0.f, int tile = 0)
{
    const int w = t >> 5, lane = t & 31;
    const int g = w & 3;
    const int e0 = (w >> 2) * 32, c0 = g * 32;
    const int pl = ((w >> 2) << 5) | lane;
    char* breg = S->bbuf + g * 8192;
    const unsigned l7 = lane & 7;
    float acc[2][4][4];
#pragma unroll
    for (int mt = 0; mt < 2; mt++)
#pragma unroll
        for (int nt = 0; nt < 4; nt++)
#pragma unroll
            for (int q = 0; q < 4; q++) acc[mt][nt][q] = 0.f;

    const unsigned arow = e0 + (lane & 15);
    const unsigned acb  = lane >> 4;
    const unsigned browl = ((lane >> 4) << 3) + l7;   // rows local to pair region
    const unsigned bcb  = (lane >> 3) & 1;
    const unsigned abh = smem_u32(Ahi) + arow * 256;
    const unsigned abl = smem_u32(Alo) + arow * 256;
    const unsigned bb  = smem_u32(breg) + browl * 256;

    CP_WAIT0();                      // W_hi region (issued by prev gemm) arrived
    BAR_PAIR(g + 1);

    // ---- pass 1: B = W_hi; hi-MMAs then lo-MMAs (acc RAW distance 8) ----
#pragma unroll
    for (int ks = 0; ks < 8; ks++) {
        unsigned ach = (((unsigned)(ks << 1)) | acb) ^ l7;
        unsigned bch = (((unsigned)(ks << 1)) | bcb) ^ l7;
        unsigned ah0[4], ah1[4], al0[4], al1[4], b0[4], b1[4];
        ldsm4(ah0, abh + (ach << 4));
        ldsm4(ah1, abh + 16 * 256 + (ach << 4));
        ldsm4(al0, abl + (ach << 4));
        ldsm4(al1, abl + 16 * 256 + (ach << 4));
        ldsm4(b0, bb + (bch << 4));
        ldsm4(b1, bb + 16 * 256 + (bch << 4));
        mma16816(acc[0][0], ah0, b0[0], b0[1]); mma16816(acc[0][1], ah0, b0[2], b0[3]);
        mma16816(acc[1][0], ah1, b0[0], b0[1]); mma16816(acc[1][1], ah1, b0[2], b0[3]);
        mma16816(acc[0][2], ah0, b1[0], b1[1]); mma16816(acc[0][3], ah0, b1[2], b1[3]);
        mma16816(acc[1][2], ah1, b1[0], b1[1]); mma16816(acc[1][3], ah1, b1[2], b1[3]);
        mma16816(acc[0][0], al0, b0[0], b0[1]); mma16816(acc[0][1], al0, b0[2], b0[3]);
        mma16816(acc[1][0], al1, b0[0], b0[1]); mma16816(acc[1][1], al1, b0[2], b0[3]);
        mma16816(acc[0][2], al0, b1[0], b1[1]); mma16816(acc[0][3], al0, b1[2], b1[3]);
        mma16816(acc[1][2], al1, b1[0], b1[1]); mma16816(acc[1][3], al1, b1[2], b1[3]);
    }
    BAR_PAIR(g + 1);                               // pair done reading W_hi
    loadBpair(breg, wcur + 16384 + g * 4096, pl);  // swap in W_lo region
    CP_WAIT0();
    BAR_PAIR(g + 1);

    // ---- pass 2: B = W_lo; A = hi only ----
#pragma unroll
    for (int ks = 0; ks < 8; ks++) {
        unsigned ach = (((unsigned)(ks << 1)) | acb) ^ l7;
        unsigned bch = (((unsigned)(ks << 1)) | bcb) ^ l7;
        unsigned ah0[4], ah1[4];
        ldsm4(ah0, abh + (ach << 4));
        ldsm4(ah1, abh + 16 * 256 + (ach << 4));
#pragma unroll
        for (int p = 0; p < 2; p++) {
            unsigned b[4];
            ldsm4(b, bb + p * 16 * 256 + (bch << 4));
            mma16816(acc[0][2 * p],     ah0, b[0], b[1]);
            mma16816(acc[0][2 * p + 1], ah0, b[2], b[3]);
            mma16816(acc[1][2 * p],     ah1, b[0], b[1]);
            mma16816(acc[1][2 * p + 1], ah1, b[2], b[3]);
        }
    }
    BAR_PAIR(g + 1);                         // pair done reading W_lo
    loadBpair(breg, wnext + g * 4096, pl);   // prefetch next matrix W_hi region

    const int r = lane >> 2, n2 = (lane & 3) * 2;
    float drow[2][2] = {{0.f, 0.f}, {0.f, 0.f}};
#pragma unroll
    for (int mt = 0; mt < 2; mt++) {
        int eA = e0 + mt * 16 + r;
#pragma unroll
        for (int nt = 0; nt < 4; nt++) {
            int c = c0 + nt * 8 + n2;
            float b0v = bias[c], b1v = bias[c + 1];
            float v00 = acc[mt][nt][0] + b0v, v01 = acc[mt][nt][1] + b1v;
            float v10 = acc[mt][nt][2] + b0v, v11 = acc[mt][nt][3] + b1v;
            if (ACT) { v00 = siluf(v00); v01 = siluf(v01);
                       v10 = siluf(v10); v11 = siluf(v11); }
            if (DOT) {
                drow[mt][0] += v00 * dw[c] + v01 * dw[c + 1];
                drow[mt][1] += v10 * dw[c] + v11 * dw[c + 1];
            }
            if (STORE) {
                st_split2(Ohi, Olo, img_off(eA, c), v00, v01);
                st_split2(Ohi, Olo, img_off(eA + 8, c), v10, v11);
            }
        }
    }
    if (DOT) {
#pragma unroll
        for (int mt = 0; mt < 2; mt++)
#pragma unroll
            for (int hb = 0; hb < 2; hb++) {
                float v = drow[mt][hb];
                v += __shfl_xor_sync(0xffffffffu, v, 1);
                v += __shfl_xor_sync(0xffffffffu, v, 2);
                if ((lane & 3) == 0)
                    S->gpart[g * TILE + e0 + mt * 16 + hb * 8 + r] = v;
            }
    }

    if (MAGG) {
        __syncthreads();                      // gpart complete across warps
        if (t < TILE) {
            bool valid = (tile * TILE + t) < EPN;
            S->gate[t] = valid ? sigmf(binf_s + S->gpart[t] + S->gpart[TILE + t]
                                       + S->gpart[2 * TILE + t] + S->gpart[3 * TILE + t])
                               : 0.f;
        }
        __syncthreads();                      // gate visible
        // magg from live acc: mc[nt][j] = sum_e m[e][c]*gate[e] over this warp's rows
        float mc[4][2];
#pragma unroll
        for (int nt = 0; nt < 4; nt++) { mc[nt][0] = 0.f; mc[nt][1] = 0.f; }
#pragma unroll
        for (int mt = 0; mt < 2; mt++) {
            float gA = S->gate[e0 + mt * 16 + r];
            float gB = S->gate[e0 + mt * 16 + 8 + r];
#pragma unroll
            for (int nt = 0; nt < 4; nt++) {
                int c = c0 + nt * 8 + n2;
                mc[nt][0] += gA * (acc[mt][nt][0] + bias[c])
                           + gB * (acc[mt][nt][2] + bias[c]);
                mc[nt][1] += gA * (acc[mt][nt][1] + bias[c + 1])
                           + gB * (acc[mt][nt][3] + bias[c + 1]);
            }
        }
#pragma unroll
        for (int nt = 0; nt < 4; nt++)
#pragma unroll
            for (int j = 0; j < 2; j++) {
                float v = mc[nt][j];
                v += __shfl_xor_sync(0xffffffffu, v, 4);
                v += __shfl_xor_sync(0xffffffffu, v, 8);
                v += __shfl_xor_sync(0xffffffffu, v, 16);
                mc[nt][j] = v;
            }
        if (lane < 4) {
            int eg = w >> 2;
#pragma unroll
            for (int nt = 0; nt < 4; nt++)
#pragma unroll
                for (int j = 0; j < 2; j++) {
                    int c = c0 + nt * 8 + lane * 2 + j;
                    S->maggs[eg * FD + c] += mc[nt][j];
                }
        }
    }
}

__global__ void __launch_bounds__(NTHR, 2)
kedge(const int* __restrict__ senders, const float* __restrict__ We0r0,
      const float* __restrict__ be1, const float* __restrict__ be2,
      const float* __restrict__ Winf, const float* __restrict__ binfp,
      const float* __restrict__ bx0, const float* __restrict__ bx1,
      const float* __restrict__ Wxo, const float* __restrict__ bxop, int blk)
{
    extern __shared__ char smraw[];
    ES* S = reinterpret_cast<ES*>(smraw);
    const int t = threadIdx.x, i = blockIdx.x;
    const int w = t >> 5, lane = t & 31;
    const int g = w & 3;
    const int pl = ((w >> 2) << 5) | lane;
    const __nv_bfloat16* wb = g_wb + blk * 4 * 32768;

    if (t < FD) {
        S->w0[t] = We0r0[t]; S->hrb[t] = g_hr[i * FD + t];
        S->winf[t] = Winf[t]; S->wxo[t] = Wxo[t];
        S->bb1[t] = be1[t]; S->bb2[t] = be2[t];
        S->bbx0[t] = bx0[t]; S->bbx1[t] = bx1[t];
    }
    S->maggs[t] = 0.f;                  // 2*FD = 256 entries
    if (t < 4) S->vaccs[t] = 0.f;
    if (t < 3) S->rvec[t] = g_vec[i * 3 + t];
    const float binf_s = binfp[0], bxo_s = bxop[0];

    loadBpair(S->bbuf + g * 8192, wb + g * 4096, pl);   // We1 hi, pair region
    __syncthreads();

    for (int tile = 0; tile < NTILE; tile++) {
        if (t < TILE) {                                  // stage 1
            int je = tile * TILE + t;
            bool valid = je < EPN;
            int s = valid ? senders[i * EPN + je] : i;
            S->sidx[t] = s;
            float d0 = 0.f, d1 = 0.f, d2 = 0.f;
            if (valid) {
                d0 = S->rvec[0] - g_vec[s * 3 + 0];
                d1 = S->rvec[1] - g_vec[s * 3 + 1];
                d2 = S->rvec[2] - g_vec[s * 3 + 2];
            }
            S->dv[t * 3] = d0; S->dv[t * 3 + 1] = d1; S->dv[t * 3 + 2] = d2;
            float dot = d0 * d0 + d1 * d1 + d2 * d2 + 1e-20f;
            S->l2[t] = valid ? dot : 0.f;
            S->len[t] = sqrtf(dot);
        }
        __syncthreads();
        {                                                // stage 2: act0 -> X
            int e = t >> 2, kh = t & 3;
            int s = S->sidx[e];
            float l2v = S->l2[e];
            const float* hsr = g_hs + s * FD + kh * 32;
#pragma unroll 8
            for (int j = 0; j < 32; j += 2) {
                int c = kh * 32 + j;
                float v0 = siluf(l2v * S->w0[c]     + hsr[j]     + S->hrb[c]);
                float v1 = siluf(l2v * S->w0[c + 1] + hsr[j + 1] + S->hrb[c + 1]);
                st_split2(S->xhi, S->xlo, img_off(e, c), v0, v1);
            }
        }
        __syncthreads();

        // G1: Y = silu(X @ We1 + be1)
        gemm_tc<true, false, true>(S, S->xhi, S->xlo,
                                   wb + 0 * 32768, wb + 1 * 32768,
                                   S->bb1, 0, S->yhi, S->ylo, t);
        __syncthreads();

        // G2: m = Y @ We2 + be2 -> X; gate + magg folded from live acc
        gemm_tc<false, true, true, true>(S, S->yhi, S->ylo,
                                   wb + 1 * 32768, wb + 2 * 32768,
                                   S->bb2, S->winf, S->xhi, S->xlo, t,
                                   binf_s, tile);
        __syncthreads();

        // G3: Y = silu(X @ Wx0 + bx0)
        gemm_tc<true, false, true>(S, S->xhi, S->xlo,
                                   wb + 2 * 32768, wb + 3 * 32768,
                                   S->bbx0, 0, S->yhi, S->ylo, t);
        __syncthreads();

        // G4: px partial = silu(Y @ Wx1 + bx1) . wxo  (no store); next = We1
        gemm_tc<true, true, false>(S, S->yhi, S->ylo,
                                   wb + 3 * 32768, wb + 0 * 32768,
                                   S->bbx1, S->wxo, S->yhi, S->ylo, t);
        __syncthreads();
        if (t < TILE)
            S->pxs[t] = __fdividef(bxo_s + S->gpart[t] + S->gpart[TILE + t]
                                   + S->gpart[2 * TILE + t] + S->gpart[3 * TILE + t],
                                   1.f + S->len[t]);
        __syncthreads();
        if (t < TILE) {                                  // vac partial
            float p = S->pxs[t];
            S->vred[t] = p * S->dv[t * 3];
            S->vred[TILE + t] = p * S->dv[t * 3 + 1];
            S->vred[2 * TILE + t] = p * S->dv[t * 3 + 2];
        }
        __syncthreads();
        if (t < 96) {
            int c = t >> 5, l = t & 31;
            const float* vr = S->vred + c * TILE;
            float v = vr[l] + vr[l + 32];
#pragma unroll
            for (int o = 16; o; o >>= 1) v += __shfl_down_sync(0xffffffffu, v, o);
            if (l == 0) S->vaccs[c] += v;
        }
        __syncthreads();
    }

    if (t < FD)
        g_magg[i * FD + t] = (S->maggs[t] + S->maggs[FD + t]) * rsqrtf(511.f);
    if (t < 3) g_vac[i * 3 + t] = S->vaccs[t] * (1.f / 511.f);
}

// weights -> T[n][k] bf16 hi/lo swizzled images (one CTA per matrix)
__global__ void __launch_bounds__(256) kwprep(
    const float* __restrict__ We1, const float* __restrict__ We2,
    const float* __restrict__ Wx0, const float* __restrict__ Wx1)
{
    int m = blockIdx.x, b = m >> 2, g = m & 3;
    const float* W = (g == 0 ? We1 : g == 1 ? We2 : g == 2 ? Wx0 : Wx1) + b * FD * FD;
    char* blob = reinterpret_cast<char*>(g_wb + m * 32768);
    int t = threadIdx.x, n = t & 127, kh = t >> 7;
    for (int kc = 0; kc < 8; kc++) {
        int kchunk = kh * 8 + kc;
        unsigned qh[4], ql[4];
#pragma unroll
        for (int u = 0; u < 4; u++) {
            int k = kchunk * 8 + u * 2;
            float x0 = W[k * FD + n], x1 = W[(k + 1) * FD + n];
            __nv_bfloat16 h0 = __float2bfloat16(x0), h1 = __float2bfloat16(x1);
            __nv_bfloat16 l0 = __float2bfloat16(x0 - __bfloat162float(h0));
            __nv_bfloat16 l1 = __float2bfloat16(x1 - __bfloat162float(h1));
            qh[u] = (unsigned)__bfloat16_as_ushort(h0) | ((unsigned)__bfloat16_as_ushort(h1) << 16);
            ql[u] = (unsigned)__bfloat16_as_ushort(l0) | ((unsigned)__bfloat16_as_ushort(l1) << 16);
        }
        int off = (n << 8) + ((kchunk ^ (n & 7)) << 4);
        *reinterpret_cast<uint4*>(blob + off)         = make_uint4(qh[0], qh[1], qh[2], qh[3]);
        *reinterpret_cast<uint4*>(blob + 32768 + off) = make_uint4(ql[0], ql[1], ql[2], ql[3]);
    }
}

__global__ void ksetup(const float* __restrict__ x)
{
    __shared__ float r0[256], r1[256], r2[256];
    __shared__ float mean[3];
    int t = threadIdx.x;
    float s0 = 0.f, s1 = 0.f, s2 = 0.f;
    for (int n = t; n < NN; n += 256) {
        s0 += x[n * 3]; s1 += x[n * 3 + 1]; s2 += x[n * 3 + 2];
    }
    r0[t] = s0; r1[t] = s1; r2[t] = s2;
    __syncthreads();
    for (int s = 128; s > 0; s >>= 1) {
        if (t < s) { r0[t] += r0[t + s]; r1[t] += r1[t + s]; r2[t] += r2[t + s]; }
        __syncthreads();
    }
    if (t == 0) { mean[0] = r0[0] / NN; mean[1] = r1[0] / NN; mean[2] = r2[0] / NN; }
    __syncthreads();
    for (int n = t; n < NN; n += 256)
#pragma unroll
        for (int c = 0; c < 3; c++) {
            float v = x[n * 3 + c] - mean[c];
            g_vec[n * 3 + c] = v; g_vec0[n * 3 + c] = v;
        }
}

__global__ void knode0(const float* __restrict__ h,
                       const float* __restrict__ Wh0, const float* __restrict__ bh0,
                       const float* __restrict__ We0, const float* __restrict__ be0)
{
    __shared__ float hrow[16];
    __shared__ float hfs[FD];
    int i = blockIdx.x, c = threadIdx.x;
    if (c < 16) hrow[c] = h[i * 16 + c];
    __syncthreads();
    float acc = bh0[c];
#pragma unroll
    for (int k = 0; k < 16; k++) acc += hrow[k] * Wh0[k * FD + c];
    g_hf[i * FD + c] = acc;
    hfs[c] = acc;
    __syncthreads();
    float s1 = 0.f, s2 = be0[c];
#pragma unroll 8
    for (int k = 0; k < FD; k++) {
        float hv = hfs[k];
        s1 += hv * We0[(1 + k) * FD + c];
        s2 += hv * We0[(129 + k) * FD + c];
    }
    g_hs[i * FD + c] = s1;
    g_hr[i * FD + c] = s2;
}

__global__ void knode(const float* __restrict__ Wp0, const float* __restrict__ bp0,
                      const float* __restrict__ Wp1, const float* __restrict__ bp1,
                      const float* __restrict__ Wpl, const float* __restrict__ bpl,
                      const float* __restrict__ We0n, const float* __restrict__ be0n,
                      int doNext)
{
    __shared__ float in0[2 * FD], t0s[FD], t1s[FD];
    int i = blockIdx.x, c = threadIdx.x;
    if (c < 3) g_vec[i * 3 + c] += g_vac[i * 3 + c];
    in0[c] = g_magg[i * FD + c];
    float hf = g_hf[i * FD + c];
    in0[FD + c] = hf;
    __syncthreads();
    float a = bp0[c];
#pragma unroll 8
    for (int k = 0; k < 2 * FD; k++) a += in0[k] * Wp0[k * FD + c];
    t0s[c] = siluf(a);
    __syncthreads();
    float b = bp1[c];
#pragma unroll 8
    for (int k = 0; k < FD; k++) b += t0s[k] * Wp1[k * FD + c];
    t1s[c] = b;
    __syncthreads();
    float d = bpl[c];
#pragma unroll 8
    for (int k = 0; k < FD; k++) d += t1s[k] * Wpl[k * FD + c];
    float nhf = hf + d;
    g_hf[i * FD + c] = nhf;
    if (doNext) {
        t0s[c] = nhf;
        __syncthreads();
        float s1 = 0.f, s2 = be0n[c];
#pragma unroll 8
        for (int k = 0; k < FD; k++) {
            float hv = t0s[k];
            s1 += hv * We0n[(1 + k) * FD + c];
            s2 += hv * We0n[(129 + k) * FD + c];
        }
        g_hs[i * FD + c] = s1;
        g_hr[i * FD + c] = s2;
    }
}

__global__ void kout(const float* __restrict__ Wv,
                     const float* __restrict__ Wr, const float* __restrict__ br,
                     float* __restrict__ out)
{
    __shared__ float red[FD], p[FD];
    int i = blockIdx.x, c = threadIdx.x;
    float hf = g_hf[i * FD + c];
    red[c] = hf;
    __syncthreads();
    for (int s = 64; s > 0; s >>= 1) {
        if (c < s) red[c] = fmaxf(red[c], red[c + s]);
        __syncthreads();
    }
    float mx = red[0];
    __syncthreads();
    float ex = __expf(hf - mx);
    red[c] = ex;
    __syncthreads();
    for (int s = 64; s > 0; s >>= 1) {
        if (c < s) red[c] += red[c + s];
        __syncthreads();
    }
    float inv = 1.f / red[0];
    __syncthreads();
    p[c] = ex * inv;
    __syncthreads();
    if (c < 32) {
        float a = br[c];
#pragma unroll 8
        for (int k = 0; k < FD; k++) a += p[k] * Wr[k * 32 + c];
        out[NN * 6 + i * 32 + c] = a;
    }
    if (c < 6) {
        int o = c / 3, cc = c % 3;
        out[i * 6 + c] = (g_vec[i * 3 + cc] - g_vec0[i * 3 + cc]) * Wv[o];
    }
}

extern "C" void kernel_launch(void* const* d_in, const int* in_sizes, int n_in,
                              void* d_out, int out_size)
{
    const float* x   = (const float*)d_in[0];
    const float* h   = (const float*)d_in[1];
    const int* snd   = (const int*)  d_in[2];
    const float* Wh0 = (const float*)d_in[4];
    const float* bh0 = (const float*)d_in[5];
    const float* We0 = (const float*)d_in[6];
    const float* be0 = (const float*)d_in[7];
    const float* We1 = (const float*)d_in[8];
    const float* be1 = (const float*)d_in[9];
    const float* We2 = (const float*)d_in[10];
    const float* be2 = (const float*)d_in[11];
    const float* Winf= (const float*)d_in[12];
    const float* binf= (const float*)d_in[13];
    const float* Wx0 = (const float*)d_in[14];
    const float* bx0 = (const float*)d_in[15];
    const float* Wx1 = (const float*)d_in[16];
    const float* bx1 = (const float*)d_in[17];
    const float* Wxo = (const float*)d_in[18];
    const float* bxo = (const float*)d_in[19];
    const float* Wp0 = (const float*)d_in[20];
    const float* bp0 = (const float*)d_in[21];
    const float* Wp1 = (const float*)d_in[22];
    const float* bp1 = (const float*)d_in[23];
    const float* Wpl = (const float*)d_in[24];
    const float* bpl = (const float*)d_in[25];
    const float* Wv  = (const float*)d_in[26];
    const float* Wr  = (const float*)d_in[27];
    const float* br  = (const float*)d_in[28];
    float* out = (float*)d_out;

    int smem = (int)sizeof(ES);
    cudaFuncSetAttribute(kedge, cudaFuncAttributeMaxDynamicSharedMemorySize, smem);

    const int WB = FD * FD, W0B = 257 * FD, WP0 = 2 * FD * FD;

    ksetup<<<1, 256>>>(x);
    knode0<<<NN, FD>>>(h, Wh0, bh0, We0, be0);
    kwprep<<<8, 256>>>(We1, We2, Wx0, Wx1);

    for (int b = 0; b < 2; b++) {
        kedge<<<NN, NTHR, smem>>>(snd, We0 + b * W0B,
            be1 + b * FD, be2 + b * FD, Winf + b * FD, binf + b,
            bx0 + b * FD, bx1 + b * FD, Wxo + b * FD, bxo + b, b);
        knode<<<NN, FD>>>(Wp0 + b * WP0, bp0 + b * FD,
                          Wp1 + b * WB, bp1 + b * FD,
                          Wpl + b * WB, bpl + b * FD,
                          We0 + W0B, be0 + FD, b == 0 ? 1 : 0);
    }
    kout<<<NN, FD>>>(Wv, Wr, br, out);
}